// round 1
// baseline (speedup 1.0000x reference)
#include <cuda_runtime.h>
#include <cuda_bf16.h>
#include <math.h>

// Problem constants
#define Bb    8
#define TQ    1024
#define TK    1024
#define DIMX  1024
#define NH    16
#define HD    64
#define SCALE 0.03125f   /* DIM^-0.5 = 1/32 */
#define NEGV  -1.0e9f
#define MROWS (Bb * TQ)  /* 8192 */

// -------- scratch (device globals: allocation-free) --------
__device__ float g_qp[(size_t)MROWS * DIMX];
__device__ float g_kp[(size_t)MROWS * DIMX];
__device__ float g_vp[(size_t)MROWS * DIMX];
__device__ unsigned char g_src8[Bb * TK];
__device__ unsigned char g_tgt8[Bb * TQ];

// ============================================================
// Mask canonicalization: masks are jax bool; the harness may hand
// them to us as uint8, int32 or float32. Detect from byte patterns
// (0x3F bytes => float32 1.0f; all bytes at offset%4!=0 zero => int32;
// else uint8) and write canonical uint8 0/1 into scratch.
// ============================================================
__global__ void mask_convert(const unsigned char* __restrict__ raw, int n, int which)
{
    __shared__ int has3F, oddNZ;
    if (threadIdx.x == 0) { has3F = 0; oddNZ = 0; }
    __syncthreads();
    int lf = 0, lo = 0;
    for (int i = threadIdx.x; i < n; i += blockDim.x) {
        unsigned char c = raw[i];
        if (c == 0x3F) lf = 1;
        if ((i & 3) && c) lo = 1;
    }
    if (lf) atomicOr(&has3F, 1);
    if (lo) atomicOr(&oddNZ, 1);
    __syncthreads();
    unsigned char* out = which ? g_tgt8 : g_src8;
    int mode = has3F ? 2 : (oddNZ ? 0 : 1);  // 2=f32, 1=i32, 0=u8
    for (int i = threadIdx.x; i < n; i += blockDim.x) {
        unsigned char v;
        if (mode == 2)      v = (((const float*)raw)[i] != 0.0f) ? 1 : 0;
        else if (mode == 1) v = (((const int*)raw)[i]   != 0)    ? 1 : 0;
        else                v = (raw[i] != 0) ? 1 : 0;
        out[i] = v;
    }
}

// ============================================================
// Projection GEMM: Y[m,n] = sum_k X[m,k]*W[n,k] + bias[n]
// M=8192, N=1024, K=1024. 128x128x8 tile, 256 threads, 8x8 micro.
// ============================================================
__global__ __launch_bounds__(256, 2)
void proj_gemm(const float* __restrict__ X, const float* __restrict__ W,
               const float* __restrict__ bias, float* __restrict__ Y)
{
    __shared__ float As[8][128];
    __shared__ float Bs[8][128];
    const int tid = threadIdx.x;
    const int bm = blockIdx.y * 128;
    const int bn = blockIdx.x * 128;
    const int tx = tid & 15, ty = tid >> 4;
    const int lr = tid >> 1;
    const int lk = (tid & 1) * 4;
    const float* Xp = X + (size_t)(bm + lr) * DIMX + lk;
    const float* Wp = W + (size_t)(bn + lr) * DIMX + lk;

    float acc[8][8];
#pragma unroll
    for (int i = 0; i < 8; i++)
#pragma unroll
        for (int j = 0; j < 8; j++) acc[i][j] = 0.0f;

    for (int k0 = 0; k0 < DIMX; k0 += 8) {
        float4 a = *(const float4*)(Xp + k0);
        float4 b = *(const float4*)(Wp + k0);
        As[lk + 0][lr] = a.x; As[lk + 1][lr] = a.y; As[lk + 2][lr] = a.z; As[lk + 3][lr] = a.w;
        Bs[lk + 0][lr] = b.x; Bs[lk + 1][lr] = b.y; Bs[lk + 2][lr] = b.z; Bs[lk + 3][lr] = b.w;
        __syncthreads();
#pragma unroll
        for (int kk = 0; kk < 8; kk++) {
            float af[8], bf[8];
            *(float4*)&af[0] = *(const float4*)&As[kk][ty * 8];
            *(float4*)&af[4] = *(const float4*)&As[kk][ty * 8 + 4];
            *(float4*)&bf[0] = *(const float4*)&Bs[kk][tx * 8];
            *(float4*)&bf[4] = *(const float4*)&Bs[kk][tx * 8 + 4];
#pragma unroll
            for (int i = 0; i < 8; i++)
#pragma unroll
                for (int j = 0; j < 8; j++)
                    acc[i][j] += af[i] * bf[j];
        }
        __syncthreads();
    }
#pragma unroll
    for (int i = 0; i < 8; i++) {
        const int row = bm + ty * 8 + i;
#pragma unroll
        for (int j = 0; j < 8; j++) {
            const int col = bn + tx * 8 + j;
            Y[(size_t)row * DIMX + col] = acc[i][j] + bias[col];
        }
    }
}

// ============================================================
// Flash attention (softmax part only; beta handled separately).
// Block = one (b, h, 64-row q tile). 256 threads, 4x4 micro tiles.
// ============================================================
struct FlashSmem {
    float Qt[HD][64];   // Qt[d][row]
    float KP[64][64];   // Kt[d][col] during S; P[p][row] after softmax
    float Vs[64][HD];   // V[p][d]
    float red[64][16];
    float rowm[64], rowl[64], rowf[64];
    unsigned char tgt[64], src[64];
};

extern __shared__ char smem_raw[];

__global__ __launch_bounds__(256)
void flash_attn(float* __restrict__ out)
{
    FlashSmem* sm = (FlashSmem*)smem_raw;
    const int tid = threadIdx.x;
    const int tx = tid & 15, ty = tid >> 4;
    const int q0 = blockIdx.x * 64;
    const int h  = blockIdx.y;
    const int b  = blockIdx.z;

    const float* qp = g_qp + (size_t)b * TQ * DIMX + h * HD;
    const float* kp = g_kp + (size_t)b * TK * DIMX + h * HD;
    const float* vp = g_vp + (size_t)b * TK * DIMX + h * HD;

    // Load Q tile (transposed: Qt[d][row])
#pragma unroll
    for (int v = tid; v < 1024; v += 256) {
        const int row = v >> 4;
        const int dq = (v & 15) * 4;
        float4 f = *(const float4*)(qp + (size_t)(q0 + row) * DIMX + dq);
        sm->Qt[dq + 0][row] = f.x; sm->Qt[dq + 1][row] = f.y;
        sm->Qt[dq + 2][row] = f.z; sm->Qt[dq + 3][row] = f.w;
    }
    if (tid < 64) {
        sm->tgt[tid]  = g_tgt8[b * TQ + q0 + tid];
        sm->rowm[tid] = -3.0e38f;
        sm->rowl[tid] = 0.0f;
    }

    float O[4][4];
#pragma unroll
    for (int i = 0; i < 4; i++)
#pragma unroll
        for (int j = 0; j < 4; j++) O[i][j] = 0.0f;

    for (int k0 = 0; k0 < TK; k0 += 64) {
        // Load K (transposed) and V (natural) chunk
#pragma unroll
        for (int v = tid; v < 1024; v += 256) {
            const int c = v >> 4;
            const int dq = (v & 15) * 4;
            float4 f = *(const float4*)(kp + (size_t)(k0 + c) * DIMX + dq);
            sm->KP[dq + 0][c] = f.x; sm->KP[dq + 1][c] = f.y;
            sm->KP[dq + 2][c] = f.z; sm->KP[dq + 3][c] = f.w;
            float4 g = *(const float4*)(vp + (size_t)(k0 + c) * DIMX + dq);
            *(float4*)&sm->Vs[c][dq] = g;
        }
        if (tid < 64) sm->src[tid] = g_src8[b * TK + k0 + tid];
        __syncthreads();

        // Stage A: S = Q @ K^T (thread holds 4x4)
        float sv[4][4];
#pragma unroll
        for (int i = 0; i < 4; i++)
#pragma unroll
            for (int j = 0; j < 4; j++) sv[i][j] = 0.0f;
#pragma unroll 16
        for (int d = 0; d < HD; d++) {
            float4 qa = *(const float4*)&sm->Qt[d][ty * 4];
            float4 ka = *(const float4*)&sm->KP[d][tx * 4];
            float qv[4] = {qa.x, qa.y, qa.z, qa.w};
            float kv[4] = {ka.x, ka.y, ka.z, ka.w};
#pragma unroll
            for (int i = 0; i < 4; i++)
#pragma unroll
                for (int j = 0; j < 4; j++)
                    sv[i][j] += qv[i] * kv[j];
        }

        // Scale + mask, partial row max
        unsigned char tg[4], sc[4];
#pragma unroll
        for (int i = 0; i < 4; i++) tg[i] = sm->tgt[ty * 4 + i];
#pragma unroll
        for (int j = 0; j < 4; j++) sc[j] = sm->src[tx * 4 + j];
        float pmax[4] = {-3.0e38f, -3.0e38f, -3.0e38f, -3.0e38f};
#pragma unroll
        for (int i = 0; i < 4; i++)
#pragma unroll
            for (int j = 0; j < 4; j++) {
                float s = sv[i][j] * SCALE;
                if (!(tg[i] && sc[j])) s = NEGV;
                sv[i][j] = s;
                pmax[i] = fmaxf(pmax[i], s);
            }
#pragma unroll
        for (int i = 0; i < 4; i++) sm->red[ty * 4 + i][tx] = pmax[i];
        __syncthreads();

        if (tid < 64) {
            float mo = sm->rowm[tid];
            float mn = mo;
#pragma unroll
            for (int t = 0; t < 16; t++) mn = fmaxf(mn, sm->red[tid][t]);
            sm->rowf[tid] = __expf(mo - mn);
            sm->rowm[tid] = mn;
        }
        __syncthreads();

        // exp + write P transposed (KP[p][row]) + partial sums
        float ps[4] = {0.f, 0.f, 0.f, 0.f};
        float mrow[4];
#pragma unroll
        for (int i = 0; i < 4; i++) mrow[i] = sm->rowm[ty * 4 + i];
#pragma unroll
        for (int i = 0; i < 4; i++)
#pragma unroll
            for (int j = 0; j < 4; j++) {
                float p = __expf(sv[i][j] - mrow[i]);
                sm->KP[tx * 4 + j][ty * 4 + i] = p;
                ps[i] += p;
            }
#pragma unroll
        for (int i = 0; i < 4; i++) sm->red[ty * 4 + i][tx] = ps[i];
        __syncthreads();

        if (tid < 64) {
            float s = 0.0f;
#pragma unroll
            for (int t = 0; t < 16; t++) s += sm->red[tid][t];
            sm->rowl[tid] = sm->rowl[tid] * sm->rowf[tid] + s;
        }

        // Stage C: O = O*f + P @ V
        float fr[4];
#pragma unroll
        for (int i = 0; i < 4; i++) fr[i] = sm->rowf[ty * 4 + i];
#pragma unroll
        for (int i = 0; i < 4; i++)
#pragma unroll
            for (int j = 0; j < 4; j++) O[i][j] *= fr[i];
#pragma unroll 8
        for (int p = 0; p < 64; p++) {
            float4 pv = *(const float4*)&sm->KP[p][ty * 4];
            float4 vv = *(const float4*)&sm->Vs[p][tx * 4];
            float pa[4] = {pv.x, pv.y, pv.z, pv.w};
            float va[4] = {vv.x, vv.y, vv.z, vv.w};
#pragma unroll
            for (int i = 0; i < 4; i++)
#pragma unroll
                for (int j = 0; j < 4; j++)
                    O[i][j] += pa[i] * va[j];
        }
        __syncthreads();
    }

    // Epilogue: divide by l and store
#pragma unroll
    for (int i = 0; i < 4; i++) {
        const int r = ty * 4 + i;
        const float inv = 1.0f / sm->rowl[r];
        float4 w;
        w.x = O[i][0] * inv; w.y = O[i][1] * inv;
        w.z = O[i][2] * inv; w.w = O[i][3] * inv;
        *(float4*)(out + ((size_t)b * TQ + q0 + r) * DIMX + h * HD + tx * 4) = w;
    }
}

// ============================================================
// beta @ V: for head h, out[b,q,h*64+d] += sum_k beta[h,q,k]*vp[b,k,h*64+d]
// M=1024(q), N=512((b,d)), K=1024. 128x128x8 tile.
// ============================================================
__global__ __launch_bounds__(256, 2)
void beta_pv(const float* __restrict__ beta, float* __restrict__ out)
{
    __shared__ float As[8][128];
    __shared__ float Bs[8][128];
    const int tid = threadIdx.x;
    const int h  = blockIdx.z;
    const int bm = blockIdx.y * 128;
    const int bn = blockIdx.x * 128;
    const int tx = tid & 15, ty = tid >> 4;
    const float* A = beta + (size_t)h * TQ * TK;

    const int lr  = tid >> 1;
    const int lk4 = (tid & 1) * 4;
    const int bk  = tid >> 5;          // 0..7
    const int nq  = (tid & 31) * 4;    // 0..124
    const int nglob = bn + nq;
    const int bb = nglob >> 6;
    const int dd = nglob & 63;
    const float* Bbase = g_vp + (size_t)bb * TK * DIMX + h * HD + dd;

    float acc[8][8];
#pragma unroll
    for (int i = 0; i < 8; i++)
#pragma unroll
        for (int j = 0; j < 8; j++) acc[i][j] = 0.0f;

    for (int k0 = 0; k0 < TK; k0 += 8) {
        float4 a = *(const float4*)(A + (size_t)(bm + lr) * TK + k0 + lk4);
        As[lk4 + 0][lr] = a.x; As[lk4 + 1][lr] = a.y;
        As[lk4 + 2][lr] = a.z; As[lk4 + 3][lr] = a.w;
        float4 bvec = *(const float4*)(Bbase + (size_t)(k0 + bk) * DIMX);
        *(float4*)&Bs[bk][nq] = bvec;
        __syncthreads();
#pragma unroll
        for (int kk = 0; kk < 8; kk++) {
            float af[8], bf[8];
            *(float4*)&af[0] = *(const float4*)&As[kk][ty * 8];
            *(float4*)&af[4] = *(const float4*)&As[kk][ty * 8 + 4];
            *(float4*)&bf[0] = *(const float4*)&Bs[kk][tx * 8];
            *(float4*)&bf[4] = *(const float4*)&Bs[kk][tx * 8 + 4];
#pragma unroll
            for (int i = 0; i < 8; i++)
#pragma unroll
                for (int j = 0; j < 8; j++)
                    acc[i][j] += af[i] * bf[j];
        }
        __syncthreads();
    }
#pragma unroll
    for (int i = 0; i < 8; i++) {
        const int row = bm + ty * 8 + i;
#pragma unroll
        for (int j = 0; j < 8; j++) {
            const int n  = bn + tx * 8 + j;
            const int b2 = n >> 6;
            const int d2 = n & 63;
            const size_t idx = ((size_t)b2 * TQ + row) * DIMX + h * HD + d2;
            out[idx] += acc[i][j];
        }
    }
}

// ============================================================
// kernel_launch
// ============================================================
extern "C" void kernel_launch(void* const* d_in, const int* in_sizes, int n_in,
                              void* d_out, int out_size)
{
    const float* q    = (const float*)d_in[0];
    const float* k    = (const float*)d_in[1];
    const float* v    = (const float*)d_in[2];
    const float* beta = (const float*)d_in[3];
    const unsigned char* srcm = (const unsigned char*)d_in[4];
    const unsigned char* tgtm = (const unsigned char*)d_in[5];
    const float* Wq = (const float*)d_in[6];
    const float* bq = (const float*)d_in[7];
    const float* Wk = (const float*)d_in[8];
    const float* bk = (const float*)d_in[9];
    const float* Wv = (const float*)d_in[10];
    const float* bv = (const float*)d_in[11];
    float* out = (float*)d_out;

    void *qp = 0, *kp = 0, *vp = 0;
    cudaGetSymbolAddress(&qp, g_qp);
    cudaGetSymbolAddress(&kp, g_kp);
    cudaGetSymbolAddress(&vp, g_vp);

    mask_convert<<<1, 1024>>>(srcm, Bb * TK, 0);
    mask_convert<<<1, 1024>>>(tgtm, Bb * TQ, 1);

    dim3 pg(DIMX / 128, MROWS / 128);
    proj_gemm<<<pg, 256>>>(q, Wq, bq, (float*)qp);
    proj_gemm<<<pg, 256>>>(k, Wk, bk, (float*)kp);
    proj_gemm<<<pg, 256>>>(v, Wv, bv, (float*)vp);

    cudaFuncSetAttribute(flash_attn, cudaFuncAttributeMaxDynamicSharedMemorySize,
                         (int)sizeof(FlashSmem));
    flash_attn<<<dim3(TQ / 64, NH, Bb), 256, sizeof(FlashSmem)>>>(out);

    beta_pv<<<dim3(512 / 128, TQ / 128, NH), 256>>>(beta, out);
}

// round 3
// speedup vs baseline: 1.7148x; 1.7148x over previous
#include <cuda_runtime.h>
#include <cuda_bf16.h>
#include <math.h>
#include <stdint.h>

// Problem constants
#define Bb    8
#define TQ    1024
#define TK    1024
#define DIMX  1024
#define NH    16
#define HD    64
#define SCALE 0.03125f
#define NEGV  -1.0e9f
#define MROWS (Bb * TQ)  /* 8192 */

// ================= PTX helpers (baseline ISA only: sm_80-era) =================
__device__ __forceinline__ uint32_t smem_u32(const void* p) {
    uint32_t a;
    asm("{ .reg .u64 t; cvta.to.shared.u64 t, %1; cvt.u32.u64 %0, t; }"
        : "=r"(a) : "l"(p));
    return a;
}
#define CP_ASYNC16(dst_u32, src_ptr) \
    asm volatile("cp.async.cg.shared.global [%0], [%1], 16;" \
        :: "r"(dst_u32), "l"(src_ptr))
#define CP_COMMIT() asm volatile("cp.async.commit_group;" ::: "memory")
#define CP_WAIT(n)  asm volatile("cp.async.wait_group %0;" :: "n"(n) : "memory")

#define LDSM4(r, addr) \
    asm volatile("ldmatrix.sync.aligned.m8n8.x4.shared.b16 {%0,%1,%2,%3}, [%4];" \
        : "=r"((r)[0]), "=r"((r)[1]), "=r"((r)[2]), "=r"((r)[3]) : "r"(addr))

#define MMA16816(c, a, b0, b1) \
    asm volatile("mma.sync.aligned.m16n8k16.row.col.f32.bf16.bf16.f32 " \
        "{%0,%1,%2,%3}, {%4,%5,%6,%7}, {%8,%9}, {%0,%1,%2,%3};" \
        : "+f"((c)[0]), "+f"((c)[1]), "+f"((c)[2]), "+f"((c)[3]) \
        : "r"((a)[0]), "r"((a)[1]), "r"((a)[2]), "r"((a)[3]), "r"(b0), "r"(b1))

// ================= scratch (device globals, 16B aligned) =================
__device__ __align__(16) float g_qp[(size_t)MROWS * DIMX];
__device__ __align__(16) float g_kp[(size_t)MROWS * DIMX];
__device__ __align__(16) float g_vp[(size_t)MROWS * DIMX];
__device__ __align__(16) __nv_bfloat16 g_ah[(size_t)16 * 1024 * 1024];  // activation/beta hi
__device__ __align__(16) __nv_bfloat16 g_al[(size_t)16 * 1024 * 1024];  // activation/beta lo
__device__ __align__(16) __nv_bfloat16 g_bh[(size_t)1024 * 1024];       // weight hi
__device__ __align__(16) __nv_bfloat16 g_bl[(size_t)1024 * 1024];       // weight lo
__device__ __align__(16) __nv_bfloat16 g_vth[(size_t)MROWS * 1024];     // V^T hi [(b,h,d)][k]
__device__ __align__(16) __nv_bfloat16 g_vtl[(size_t)MROWS * 1024];     // V^T lo
__device__ unsigned char g_src8[Bb * TK];
__device__ unsigned char g_tgt8[Bb * TQ];

// ================= mask canonicalization =================
__global__ void mask_convert(const unsigned char* __restrict__ raw, int n, int which)
{
    __shared__ int has3F, oddNZ;
    if (threadIdx.x == 0) { has3F = 0; oddNZ = 0; }
    __syncthreads();
    int lf = 0, lo = 0;
    for (int i = threadIdx.x; i < n; i += blockDim.x) {
        unsigned char c = raw[i];
        if (c == 0x3F) lf = 1;
        if ((i & 3) && c) lo = 1;
    }
    if (lf) atomicOr(&has3F, 1);
    if (lo) atomicOr(&oddNZ, 1);
    __syncthreads();
    unsigned char* out = which ? g_tgt8 : g_src8;
    int mode = has3F ? 2 : (oddNZ ? 0 : 1);
    for (int i = threadIdx.x; i < n; i += blockDim.x) {
        unsigned char v;
        if (mode == 2)      v = (((const float*)raw)[i] != 0.0f) ? 1 : 0;
        else if (mode == 1) v = (((const int*)raw)[i]   != 0)    ? 1 : 0;
        else                v = (raw[i] != 0) ? 1 : 0;
        out[i] = v;
    }
}

// ================= fp32 -> (bf16 hi, bf16 lo) split =================
__global__ __launch_bounds__(256)
void conv_split(const float4* __restrict__ x, __nv_bfloat16* __restrict__ hi,
                __nv_bfloat16* __restrict__ lo, int n4)
{
    int i = blockIdx.x * 256 + threadIdx.x;
    if (i >= n4) return;
    float4 f = x[i];
    __nv_bfloat16 h0 = __float2bfloat16_rn(f.x);
    __nv_bfloat16 h1 = __float2bfloat16_rn(f.y);
    __nv_bfloat16 h2 = __float2bfloat16_rn(f.z);
    __nv_bfloat16 h3 = __float2bfloat16_rn(f.w);
    __nv_bfloat16 l0 = __float2bfloat16_rn(f.x - __bfloat162float(h0));
    __nv_bfloat16 l1 = __float2bfloat16_rn(f.y - __bfloat162float(h1));
    __nv_bfloat16 l2 = __float2bfloat16_rn(f.z - __bfloat162float(h2));
    __nv_bfloat16 l3 = __float2bfloat16_rn(f.w - __bfloat162float(h3));
    __nv_bfloat162* Hp = (__nv_bfloat162*)(hi + 4 * (size_t)i);
    __nv_bfloat162* Lp = (__nv_bfloat162*)(lo + 4 * (size_t)i);
    Hp[0] = __halves2bfloat162(h0, h1);
    Hp[1] = __halves2bfloat162(h2, h3);
    Lp[0] = __halves2bfloat162(l0, l1);
    Lp[1] = __halves2bfloat162(l2, l3);
}

// ================= V transpose + split: g_vp -> g_vth/g_vtl =================
__global__ __launch_bounds__(256)
void vtrans()
{
    __shared__ float T[64][65];
    const int tid = threadIdx.x;
    const int t0 = blockIdx.x * 64;
    const int h  = blockIdx.y;
    const int b  = blockIdx.z;
    const float* src = g_vp + ((size_t)b * 1024 + t0) * DIMX + h * HD;
#pragma unroll
    for (int i = 0; i < 4; i++) {
        int idx = tid + i * 256;
        int tl = idx >> 4, d4 = (idx & 15) * 4;
        float4 f = *(const float4*)(src + (size_t)tl * DIMX + d4);
        T[tl][d4 + 0] = f.x; T[tl][d4 + 1] = f.y;
        T[tl][d4 + 2] = f.z; T[tl][d4 + 3] = f.w;
    }
    __syncthreads();
#pragma unroll
    for (int i = 0; i < 4; i++) {
        int idx = tid + i * 256;
        int dl = idx >> 4, t4 = (idx & 15) * 4;
        size_t row = ((size_t)b * 16 + h) * 64 + dl;
        __nv_bfloat16 hv[4], lv[4];
#pragma unroll
        for (int j = 0; j < 4; j++) {
            float e = T[t4 + j][dl];
            hv[j] = __float2bfloat16_rn(e);
            lv[j] = __float2bfloat16_rn(e - __bfloat162float(hv[j]));
        }
        __nv_bfloat162* Hp = (__nv_bfloat162*)(g_vth + row * 1024 + t0 + t4);
        __nv_bfloat162* Lp = (__nv_bfloat162*)(g_vtl + row * 1024 + t0 + t4);
        Hp[0] = __halves2bfloat162(hv[0], hv[1]);
        Hp[1] = __halves2bfloat162(hv[2], hv[3]);
        Lp[0] = __halves2bfloat162(lv[0], lv[1]);
        Lp[1] = __halves2bfloat162(lv[2], lv[3]);
    }
}

// ================= mma.sync split-bf16 GEMM =================
// MODE 0 (projection): Y[bm+128, bn+128] = A[8192,1024] @ B[1024,1024]^T + bias
// MODE 1 (beta@V):     out[b, bm+q, h*64+d] += beta_h @ vth^T
// Block 128x128, BK=64, 8 warps of 64x32, cp.async double buffer.
#define NKCH 16
#define STG_B 65536            /* Ah16K Al16K Bh16K Bl16K */
#define GSMEM_TOTAL (2 * STG_B)

extern __shared__ char smem_raw[];

template <int MODE>
__global__ __launch_bounds__(256)
void gemm_mma(const __nv_bfloat16* __restrict__ Ahg, const __nv_bfloat16* __restrict__ Alg,
              const __nv_bfloat16* __restrict__ Bhg, const __nv_bfloat16* __restrict__ Blg,
              const float* __restrict__ bias, float* __restrict__ Y)
{
    const uint32_t sb = smem_u32(smem_raw);
    const int tid  = threadIdx.x;
    const int wid  = tid >> 5;
    const int lane = tid & 31;
    const int wm = (wid >> 2) * 64;   // 0 / 64
    const int wn = (wid & 3) * 32;    // 0..96

    int bm, bn = 0, h = 0, b0 = 0;
    size_t arow0;
    if (MODE == 0) {
        bn = blockIdx.x * 128; bm = blockIdx.y * 128;
        arow0 = (size_t)bm;
    } else {
        b0 = blockIdx.x * 2; bm = blockIdx.y * 128; h = blockIdx.z;
        arow0 = (size_t)h * 1024 + bm;
    }

    float C[4][4][4];
#pragma unroll
    for (int i = 0; i < 4; i++)
#pragma unroll
        for (int j = 0; j < 4; j++)
#pragma unroll
            for (int r = 0; r < 4; r++) C[i][j][r] = 0.0f;

    // ---- async stage loader ----
    auto load_stage = [&](int s, int kc) {
        const uint32_t st = sb + s * STG_B;
        const int koff = kc * 64;
#pragma unroll
        for (int i = 0; i < 4; i++) {
            int idx = tid + i * 256;
            int row = idx >> 3, c = idx & 7;
            uint32_t off = row * 128 + c * 16;
            uint32_t sw = off ^ ((off >> 3) & 0x70);
            size_t gA = (arow0 + row) * 1024 + koff + c * 8;
            CP_ASYNC16(st + sw,          Ahg + gA);
            CP_ASYNC16(st + 16384 + sw,  Alg + gA);
            int grow = (MODE == 0) ? (bn + row)
                                   : (((b0 + (row >> 6)) * 16 + h) * 64 + (row & 63));
            size_t gB = (size_t)grow * 1024 + koff + c * 8;
            CP_ASYNC16(st + 32768 + sw,  Bhg + gB);
            CP_ASYNC16(st + 49152 + sw,  Blg + gB);
        }
        CP_COMMIT();
    };

    // per-lane ldmatrix address components
    const int q  = lane >> 3;
    const int lr = lane & 7;
    const int am_row = wm + (q & 1) * 8 + lr;   // + i*16
    const int a_kq   = (q >> 1) * 16;           // byte offset within k-chunk
    const int bn_row = wn + (q >> 1) * 8 + lr;  // + j2*16
    const int b_kq   = (q & 1) * 16;

    load_stage(0, 0);

    for (int kc = 0; kc < NKCH; kc++) {
        if (kc + 1 < NKCH) { load_stage((kc + 1) & 1, kc + 1); CP_WAIT(1); }
        else               { CP_WAIT(0); }
        __syncthreads();

        const uint32_t st = sb + (kc & 1) * STG_B;
#pragma unroll
        for (int ks = 0; ks < 4; ks++) {
            uint32_t aH[4][4], aL[4][4], bH[2][4], bL[2][4];
#pragma unroll
            for (int i = 0; i < 4; i++) {
                uint32_t off = (uint32_t)(am_row + i * 16) * 128 + a_kq + ks * 32;
                uint32_t sw = off ^ ((off >> 3) & 0x70);
                LDSM4(aH[i], st + sw);
                LDSM4(aL[i], st + 16384 + sw);
            }
#pragma unroll
            for (int j2 = 0; j2 < 2; j2++) {
                uint32_t off = (uint32_t)(bn_row + j2 * 16) * 128 + b_kq + ks * 32;
                uint32_t sw = off ^ ((off >> 3) & 0x70);
                LDSM4(bH[j2], st + 32768 + sw);
                LDSM4(bL[j2], st + 49152 + sw);
            }
#pragma unroll
            for (int i = 0; i < 4; i++)
#pragma unroll
                for (int j = 0; j < 4; j++) {
                    const int jj = j >> 1, jo = (j & 1) * 2;
                    MMA16816(C[i][j], aH[i], bH[jj][jo], bH[jj][jo + 1]);
                    MMA16816(C[i][j], aH[i], bL[jj][jo], bL[jj][jo + 1]);
                    MMA16816(C[i][j], aL[i], bH[jj][jo], bH[jj][jo + 1]);
                }
        }
        __syncthreads();
    }

    // ---- epilogue ----
    const int g  = lane >> 2;
    const int tg = lane & 3;
#pragma unroll
    for (int i = 0; i < 4; i++) {
#pragma unroll
        for (int j = 0; j < 4; j++) {
            const int ncol = wn + j * 8 + tg * 2;   // 0..127 (even)
            const int r0 = bm + wm + i * 16 + g;
            const int r1 = r0 + 8;
            if (MODE == 0) {
                const int col = bn + ncol;
                float b0v = bias[col], b1v = bias[col + 1];
                float2 w0 = make_float2(C[i][j][0] + b0v, C[i][j][1] + b1v);
                float2 w1 = make_float2(C[i][j][2] + b0v, C[i][j][3] + b1v);
                *(float2*)(Y + (size_t)r0 * 1024 + col) = w0;
                *(float2*)(Y + (size_t)r1 * 1024 + col) = w1;
            } else {
                const int n = blockIdx.x * 128 + ncol;
                const int bb = n >> 6, dd = n & 63;
                float* p0 = Y + ((size_t)bb * 1024 + r0) * 1024 + h * 64 + dd;
                float* p1 = Y + ((size_t)bb * 1024 + r1) * 1024 + h * 64 + dd;
                float2 o0 = *(float2*)p0, o1 = *(float2*)p1;
                o0.x += C[i][j][0]; o0.y += C[i][j][1];
                o1.x += C[i][j][2]; o1.y += C[i][j][3];
                *(float2*)p0 = o0;
                *(float2*)p1 = o1;
            }
        }
    }
}

// ================= flash attention (fp32 SIMT) =================
struct FlashSmem {
    float Qt[HD][64];
    float KP[64][64];
    float Vs[64][HD];
    float red[64][16];
    float rowm[64], rowl[64], rowf[64];
    unsigned char tgt[64], src[64];
};

__global__ __launch_bounds__(256)
void flash_attn(float* __restrict__ out)
{
    FlashSmem* sm = (FlashSmem*)smem_raw;
    const int tid = threadIdx.x;
    const int tx = tid & 15, ty = tid >> 4;
    const int q0 = blockIdx.x * 64;
    const int h  = blockIdx.y;
    const int b  = blockIdx.z;

    const float* qp = g_qp + (size_t)b * TQ * DIMX + h * HD;
    const float* kp = g_kp + (size_t)b * TK * DIMX + h * HD;
    const float* vp = g_vp + (size_t)b * TK * DIMX + h * HD;

#pragma unroll
    for (int v = tid; v < 1024; v += 256) {
        const int row = v >> 4;
        const int dq = (v & 15) * 4;
        float4 f = *(const float4*)(qp + (size_t)(q0 + row) * DIMX + dq);
        sm->Qt[dq + 0][row] = f.x; sm->Qt[dq + 1][row] = f.y;
        sm->Qt[dq + 2][row] = f.z; sm->Qt[dq + 3][row] = f.w;
    }
    if (tid < 64) {
        sm->tgt[tid]  = g_tgt8[b * TQ + q0 + tid];
        sm->rowm[tid] = -3.0e38f;
        sm->rowl[tid] = 0.0f;
    }

    float O[4][4];
#pragma unroll
    for (int i = 0; i < 4; i++)
#pragma unroll
        for (int j = 0; j < 4; j++) O[i][j] = 0.0f;

    for (int k0 = 0; k0 < TK; k0 += 64) {
#pragma unroll
        for (int v = tid; v < 1024; v += 256) {
            const int c = v >> 4;
            const int dq = (v & 15) * 4;
            float4 f = *(const float4*)(kp + (size_t)(k0 + c) * DIMX + dq);
            sm->KP[dq + 0][c] = f.x; sm->KP[dq + 1][c] = f.y;
            sm->KP[dq + 2][c] = f.z; sm->KP[dq + 3][c] = f.w;
            float4 g = *(const float4*)(vp + (size_t)(k0 + c) * DIMX + dq);
            *(float4*)&sm->Vs[c][dq] = g;
        }
        if (tid < 64) sm->src[tid] = g_src8[b * TK + k0 + tid];
        __syncthreads();

        float sv[4][4];
#pragma unroll
        for (int i = 0; i < 4; i++)
#pragma unroll
            for (int j = 0; j < 4; j++) sv[i][j] = 0.0f;
#pragma unroll 16
        for (int d = 0; d < HD; d++) {
            float4 qa = *(const float4*)&sm->Qt[d][ty * 4];
            float4 ka = *(const float4*)&sm->KP[d][tx * 4];
            float qv[4] = {qa.x, qa.y, qa.z, qa.w};
            float kv[4] = {ka.x, ka.y, ka.z, ka.w};
#pragma unroll
            for (int i = 0; i < 4; i++)
#pragma unroll
                for (int j = 0; j < 4; j++)
                    sv[i][j] += qv[i] * kv[j];
        }

        unsigned char tg[4], sc[4];
#pragma unroll
        for (int i = 0; i < 4; i++) tg[i] = sm->tgt[ty * 4 + i];
#pragma unroll
        for (int j = 0; j < 4; j++) sc[j] = sm->src[tx * 4 + j];
        float pmax[4] = {-3.0e38f, -3.0e38f, -3.0e38f, -3.0e38f};
#pragma unroll
        for (int i = 0; i < 4; i++)
#pragma unroll
            for (int j = 0; j < 4; j++) {
                float s = sv[i][j] * SCALE;
                if (!(tg[i] && sc[j])) s = NEGV;
                sv[i][j] = s;
                pmax[i] = fmaxf(pmax[i], s);
            }
#pragma unroll
        for (int i = 0; i < 4; i++) sm->red[ty * 4 + i][tx] = pmax[i];
        __syncthreads();

        if (tid < 64) {
            float mo = sm->rowm[tid];
            float mn = mo;
#pragma unroll
            for (int t = 0; t < 16; t++) mn = fmaxf(mn, sm->red[tid][t]);
            sm->rowf[tid] = __expf(mo - mn);
            sm->rowm[tid] = mn;
        }
        __syncthreads();

        float ps[4] = {0.f, 0.f, 0.f, 0.f};
        float mrow[4];
#pragma unroll
        for (int i = 0; i < 4; i++) mrow[i] = sm->rowm[ty * 4 + i];
#pragma unroll
        for (int i = 0; i < 4; i++)
#pragma unroll
            for (int j = 0; j < 4; j++) {
                float p = __expf(sv[i][j] - mrow[i]);
                sm->KP[tx * 4 + j][ty * 4 + i] = p;
                ps[i] += p;
            }
#pragma unroll
        for (int i = 0; i < 4; i++) sm->red[ty * 4 + i][tx] = ps[i];
        __syncthreads();

        if (tid < 64) {
            float s = 0.0f;
#pragma unroll
            for (int t = 0; t < 16; t++) s += sm->red[tid][t];
            sm->rowl[tid] = sm->rowl[tid] * sm->rowf[tid] + s;
        }

        float fr[4];
#pragma unroll
        for (int i = 0; i < 4; i++) fr[i] = sm->rowf[ty * 4 + i];
#pragma unroll
        for (int i = 0; i < 4; i++)
#pragma unroll
            for (int j = 0; j < 4; j++) O[i][j] *= fr[i];
#pragma unroll 8
        for (int p = 0; p < 64; p++) {
            float4 pv = *(const float4*)&sm->KP[p][ty * 4];
            float4 vv = *(const float4*)&sm->Vs[p][tx * 4];
            float pa[4] = {pv.x, pv.y, pv.z, pv.w};
            float va[4] = {vv.x, vv.y, vv.z, vv.w};
#pragma unroll
            for (int i = 0; i < 4; i++)
#pragma unroll
                for (int j = 0; j < 4; j++)
                    O[i][j] += pa[i] * va[j];
        }
        __syncthreads();
    }

#pragma unroll
    for (int i = 0; i < 4; i++) {
        const int r = ty * 4 + i;
        const float inv = 1.0f / sm->rowl[r];
        float4 w;
        w.x = O[i][0] * inv; w.y = O[i][1] * inv;
        w.z = O[i][2] * inv; w.w = O[i][3] * inv;
        *(float4*)(out + ((size_t)b * TQ + q0 + r) * DIMX + h * HD + tx * 4) = w;
    }
}

// ================= kernel_launch =================
extern "C" void kernel_launch(void* const* d_in, const int* in_sizes, int n_in,
                              void* d_out, int out_size)
{
    const float* q    = (const float*)d_in[0];
    const float* k    = (const float*)d_in[1];
    const float* v    = (const float*)d_in[2];
    const float* beta = (const float*)d_in[3];
    const unsigned char* srcm = (const unsigned char*)d_in[4];
    const unsigned char* tgtm = (const unsigned char*)d_in[5];
    const float* Wq = (const float*)d_in[6];
    const float* bq = (const float*)d_in[7];
    const float* Wk = (const float*)d_in[8];
    const float* bk = (const float*)d_in[9];
    const float* Wv = (const float*)d_in[10];
    const float* bv = (const float*)d_in[11];
    float* out = (float*)d_out;

    void *qp, *kp, *vp, *ah, *al, *bh, *bl, *vth, *vtl;
    cudaGetSymbolAddress(&qp, g_qp);
    cudaGetSymbolAddress(&kp, g_kp);
    cudaGetSymbolAddress(&vp, g_vp);
    cudaGetSymbolAddress(&ah, g_ah);
    cudaGetSymbolAddress(&al, g_al);
    cudaGetSymbolAddress(&bh, g_bh);
    cudaGetSymbolAddress(&bl, g_bl);
    cudaGetSymbolAddress(&vth, g_vth);
    cudaGetSymbolAddress(&vtl, g_vtl);

    cudaFuncSetAttribute(gemm_mma<0>, cudaFuncAttributeMaxDynamicSharedMemorySize, GSMEM_TOTAL);
    cudaFuncSetAttribute(gemm_mma<1>, cudaFuncAttributeMaxDynamicSharedMemorySize, GSMEM_TOTAL);
    cudaFuncSetAttribute(flash_attn, cudaFuncAttributeMaxDynamicSharedMemorySize, (int)sizeof(FlashSmem));

    mask_convert<<<1, 1024>>>(srcm, Bb * TK, 0);
    mask_convert<<<1, 1024>>>(tgtm, Bb * TQ, 1);

    const int n4_act  = (MROWS * DIMX) / 4;
    const int n4_w    = (DIMX * DIMX) / 4;
    const int n4_beta = (NH * TQ * TK) / 4;
    dim3 pgrid(8, 64);

    // Q projection
    conv_split<<<(n4_act + 255) / 256, 256>>>((const float4*)q, (__nv_bfloat16*)ah, (__nv_bfloat16*)al, n4_act);
    conv_split<<<(n4_w + 255) / 256, 256>>>((const float4*)Wq, (__nv_bfloat16*)bh, (__nv_bfloat16*)bl, n4_w);
    gemm_mma<0><<<pgrid, 256, GSMEM_TOTAL>>>((const __nv_bfloat16*)ah, (const __nv_bfloat16*)al,
                                             (const __nv_bfloat16*)bh, (const __nv_bfloat16*)bl,
                                             bq, (float*)qp);
    // K projection
    conv_split<<<(n4_act + 255) / 256, 256>>>((const float4*)k, (__nv_bfloat16*)ah, (__nv_bfloat16*)al, n4_act);
    conv_split<<<(n4_w + 255) / 256, 256>>>((const float4*)Wk, (__nv_bfloat16*)bh, (__nv_bfloat16*)bl, n4_w);
    gemm_mma<0><<<pgrid, 256, GSMEM_TOTAL>>>((const __nv_bfloat16*)ah, (const __nv_bfloat16*)al,
                                             (const __nv_bfloat16*)bh, (const __nv_bfloat16*)bl,
                                             bk, (float*)kp);
    // V projection
    conv_split<<<(n4_act + 255) / 256, 256>>>((const float4*)v, (__nv_bfloat16*)ah, (__nv_bfloat16*)al, n4_act);
    conv_split<<<(n4_w + 255) / 256, 256>>>((const float4*)Wv, (__nv_bfloat16*)bh, (__nv_bfloat16*)bl, n4_w);
    gemm_mma<0><<<pgrid, 256, GSMEM_TOTAL>>>((const __nv_bfloat16*)ah, (const __nv_bfloat16*)al,
                                             (const __nv_bfloat16*)bh, (const __nv_bfloat16*)bl,
                                             bv, (float*)vp);

    // flash attention writes out
    flash_attn<<<dim3(TQ / 64, NH, Bb), 256, sizeof(FlashSmem)>>>(out);

    // beta @ V accumulated into out
    vtrans<<<dim3(16, 16, 8), 256>>>();
    conv_split<<<(n4_beta + 255) / 256, 256>>>((const float4*)beta, (__nv_bfloat16*)ah, (__nv_bfloat16*)al, n4_beta);
    gemm_mma<1><<<dim3(4, 8, 16), 256, GSMEM_TOTAL>>>((const __nv_bfloat16*)ah, (const __nv_bfloat16*)al,
                                                      (const __nv_bfloat16*)vth, (const __nv_bfloat16*)vtl,
                                                      nullptr, out);
}

// round 4
// speedup vs baseline: 3.2436x; 1.8915x over previous
#include <cuda_runtime.h>
#include <cuda_bf16.h>
#include <math.h>
#include <stdint.h>

// Problem constants
#define Bb    8
#define TQ    1024
#define TK    1024
#define DIMX  1024
#define NH    16
#define HD    64
#define SCALE 0.03125f
#define NEGV  -1.0e9f
#define MROWS (Bb * TQ)  /* 8192 */

// ================= PTX helpers (baseline ISA only) =================
__device__ __forceinline__ uint32_t smem_u32(const void* p) {
    uint32_t a;
    asm("{ .reg .u64 t; cvta.to.shared.u64 t, %1; cvt.u32.u64 %0, t; }"
        : "=r"(a) : "l"(p));
    return a;
}
#define CP_ASYNC16(dst_u32, src_ptr) \
    asm volatile("cp.async.cg.shared.global [%0], [%1], 16;" \
        :: "r"(dst_u32), "l"(src_ptr))
#define CP_COMMIT() asm volatile("cp.async.commit_group;" ::: "memory")
#define CP_WAIT(n)  asm volatile("cp.async.wait_group %0;" :: "n"(n) : "memory")

#define LDSM4(r, addr) \
    asm volatile("ldmatrix.sync.aligned.m8n8.x4.shared.b16 {%0,%1,%2,%3}, [%4];" \
        : "=r"((r)[0]), "=r"((r)[1]), "=r"((r)[2]), "=r"((r)[3]) : "r"(addr))
#define LDSM4T(r, addr) \
    asm volatile("ldmatrix.sync.aligned.m8n8.x4.trans.shared.b16 {%0,%1,%2,%3}, [%4];" \
        : "=r"((r)[0]), "=r"((r)[1]), "=r"((r)[2]), "=r"((r)[3]) : "r"(addr))

#define MMA16816(c, a, b0, b1) \
    asm volatile("mma.sync.aligned.m16n8k16.row.col.f32.bf16.bf16.f32 " \
        "{%0,%1,%2,%3}, {%4,%5,%6,%7}, {%8,%9}, {%0,%1,%2,%3};" \
        : "+f"((c)[0]), "+f"((c)[1]), "+f"((c)[2]), "+f"((c)[3]) \
        : "r"((a)[0]), "r"((a)[1]), "r"((a)[2]), "r"((a)[3]), "r"(b0), "r"(b1))

// pack two fp32 -> bf16x2 (lo -> lower half, hi -> upper half)
__device__ __forceinline__ uint32_t pbf2(float lo, float hi) {
    uint32_t d;
    asm("cvt.rn.bf16x2.f32 %0, %1, %2;" : "=r"(d) : "f"(hi), "f"(lo));
    return d;
}

// ================= scratch (device globals, 16B aligned) =================
__device__ __align__(16) __nv_bfloat16 g_qph[(size_t)MROWS * DIMX];
__device__ __align__(16) __nv_bfloat16 g_qpl[(size_t)MROWS * DIMX];
__device__ __align__(16) __nv_bfloat16 g_kph[(size_t)MROWS * DIMX];
__device__ __align__(16) __nv_bfloat16 g_kpl[(size_t)MROWS * DIMX];
__device__ __align__(16) __nv_bfloat16 g_vph[(size_t)MROWS * DIMX];
__device__ __align__(16) __nv_bfloat16 g_vpl[(size_t)MROWS * DIMX];
__device__ __align__(16) __nv_bfloat16 g_ah[(size_t)16 * 1024 * 1024];
__device__ __align__(16) __nv_bfloat16 g_al[(size_t)16 * 1024 * 1024];
__device__ __align__(16) __nv_bfloat16 g_bh[(size_t)1024 * 1024];
__device__ __align__(16) __nv_bfloat16 g_bl[(size_t)1024 * 1024];
__device__ __align__(16) __nv_bfloat16 g_vth[(size_t)MROWS * 1024];   // V^T hi [(b,h,d)][k]
__device__ __align__(16) __nv_bfloat16 g_vtl[(size_t)MROWS * 1024];
__device__ unsigned char g_src8[Bb * TK];
__device__ unsigned char g_tgt8[Bb * TQ];

// ================= mask canonicalization =================
__global__ void mask_convert(const unsigned char* __restrict__ raw, int n, int which)
{
    __shared__ int has3F, oddNZ;
    if (threadIdx.x == 0) { has3F = 0; oddNZ = 0; }
    __syncthreads();
    int lf = 0, lo = 0;
    for (int i = threadIdx.x; i < n; i += blockDim.x) {
        unsigned char c = raw[i];
        if (c == 0x3F) lf = 1;
        if ((i & 3) && c) lo = 1;
    }
    if (lf) atomicOr(&has3F, 1);
    if (lo) atomicOr(&oddNZ, 1);
    __syncthreads();
    unsigned char* out = which ? g_tgt8 : g_src8;
    int mode = has3F ? 2 : (oddNZ ? 0 : 1);
    for (int i = threadIdx.x; i < n; i += blockDim.x) {
        unsigned char v;
        if (mode == 2)      v = (((const float*)raw)[i] != 0.0f) ? 1 : 0;
        else if (mode == 1) v = (((const int*)raw)[i]   != 0)    ? 1 : 0;
        else                v = (raw[i] != 0) ? 1 : 0;
        out[i] = v;
    }
}

// ================= fp32 -> (bf16 hi, bf16 lo) split =================
__global__ __launch_bounds__(256)
void conv_split(const float4* __restrict__ x, __nv_bfloat16* __restrict__ hi,
                __nv_bfloat16* __restrict__ lo, int n4)
{
    int i = blockIdx.x * 256 + threadIdx.x;
    if (i >= n4) return;
    float4 f = x[i];
    __nv_bfloat16 h0 = __float2bfloat16_rn(f.x);
    __nv_bfloat16 h1 = __float2bfloat16_rn(f.y);
    __nv_bfloat16 h2 = __float2bfloat16_rn(f.z);
    __nv_bfloat16 h3 = __float2bfloat16_rn(f.w);
    __nv_bfloat16 l0 = __float2bfloat16_rn(f.x - __bfloat162float(h0));
    __nv_bfloat16 l1 = __float2bfloat16_rn(f.y - __bfloat162float(h1));
    __nv_bfloat16 l2 = __float2bfloat16_rn(f.z - __bfloat162float(h2));
    __nv_bfloat16 l3 = __float2bfloat16_rn(f.w - __bfloat162float(h3));
    __nv_bfloat162* Hp = (__nv_bfloat162*)(hi + 4 * (size_t)i);
    __nv_bfloat162* Lp = (__nv_bfloat162*)(lo + 4 * (size_t)i);
    Hp[0] = __halves2bfloat162(h0, h1);
    Hp[1] = __halves2bfloat162(h2, h3);
    Lp[0] = __halves2bfloat162(l0, l1);
    Lp[1] = __halves2bfloat162(l2, l3);
}

// ================= V transpose (bf16): g_vph/l -> g_vth/l =================
__global__ __launch_bounds__(256)
void vtrans()
{
    __shared__ unsigned short Th[64][72];
    __shared__ unsigned short Tl[64][72];
    const int tid = threadIdx.x;
    const int t0 = blockIdx.x * 64;
    const int h  = blockIdx.y;
    const int b  = blockIdx.z;
    const unsigned short* srcH = (const unsigned short*)g_vph + ((size_t)b * 1024 + t0) * 1024 + h * 64;
    const unsigned short* srcL = (const unsigned short*)g_vpl + ((size_t)b * 1024 + t0) * 1024 + h * 64;
#pragma unroll
    for (int i = 0; i < 2; i++) {
        int idx = tid + i * 256;
        int row = idx >> 3, c = idx & 7;
        *(uint4*)&Th[row][c * 8] = *(const uint4*)(srcH + (size_t)row * 1024 + c * 8);
        *(uint4*)&Tl[row][c * 8] = *(const uint4*)(srcL + (size_t)row * 1024 + c * 8);
    }
    __syncthreads();
#pragma unroll
    for (int i = 0; i < 2; i++) {
        int idx = tid + i * 256;
        int dl = idx >> 3, t8 = (idx & 7) * 8;
        __align__(16) unsigned short vh[8], vl8[8];
#pragma unroll
        for (int j = 0; j < 8; j++) { vh[j] = Th[t8 + j][dl]; vl8[j] = Tl[t8 + j][dl]; }
        size_t row = ((size_t)b * 16 + h) * 64 + dl;
        *(uint4*)((unsigned short*)g_vth + row * 1024 + t0 + t8) = *(uint4*)vh;
        *(uint4*)((unsigned short*)g_vtl + row * 1024 + t0 + t8) = *(uint4*)vl8;
    }
}

// ================= mma.sync split-bf16 GEMM =================
// MODE 0: Yh/Yl[bm+128, bn+128] = bf16split(A @ B^T + bias)
// MODE 1: Yf(out)[b, bm+q, h*64+d] += beta_h @ vth^T
#define NKCH 16
#define STG_B 65536
#define GSMEM_TOTAL (2 * STG_B)

extern __shared__ char smem_raw[];

template <int MODE>
__global__ __launch_bounds__(256)
void gemm_mma(const __nv_bfloat16* __restrict__ Ahg, const __nv_bfloat16* __restrict__ Alg,
              const __nv_bfloat16* __restrict__ Bhg, const __nv_bfloat16* __restrict__ Blg,
              const float* __restrict__ bias,
              __nv_bfloat16* __restrict__ Yh, __nv_bfloat16* __restrict__ Yl,
              float* __restrict__ Yf)
{
    const uint32_t sb = smem_u32(smem_raw);
    const int tid  = threadIdx.x;
    const int lane = tid & 31;
    const int wid  = tid >> 5;
    const int wm = (wid >> 2) * 64;
    const int wn = (wid & 3) * 32;

    int bm, bn = 0, h = 0, b0 = 0;
    size_t arow0;
    if (MODE == 0) {
        bn = blockIdx.x * 128; bm = blockIdx.y * 128;
        arow0 = (size_t)bm;
    } else {
        b0 = blockIdx.x * 2; bm = blockIdx.y * 128; h = blockIdx.z;
        arow0 = (size_t)h * 1024 + bm;
    }

    float C[4][4][4];
#pragma unroll
    for (int i = 0; i < 4; i++)
#pragma unroll
        for (int j = 0; j < 4; j++)
#pragma unroll
            for (int r = 0; r < 4; r++) C[i][j][r] = 0.0f;

    auto load_stage = [&](int s, int kc) {
        const uint32_t st = sb + s * STG_B;
        const int koff = kc * 64;
#pragma unroll
        for (int i = 0; i < 4; i++) {
            int idx = tid + i * 256;
            int row = idx >> 3, c = idx & 7;
            uint32_t off = row * 128 + c * 16;
            uint32_t sw = off ^ ((off >> 3) & 0x70);
            size_t gA = (arow0 + row) * 1024 + koff + c * 8;
            CP_ASYNC16(st + sw,          Ahg + gA);
            CP_ASYNC16(st + 16384 + sw,  Alg + gA);
            int grow = (MODE == 0) ? (bn + row)
                                   : (((b0 + (row >> 6)) * 16 + h) * 64 + (row & 63));
            size_t gB = (size_t)grow * 1024 + koff + c * 8;
            CP_ASYNC16(st + 32768 + sw,  Bhg + gB);
            CP_ASYNC16(st + 49152 + sw,  Blg + gB);
        }
        CP_COMMIT();
    };

    const int q  = lane >> 3;
    const int lr = lane & 7;
    const int am_row = wm + (q & 1) * 8 + lr;
    const int a_kq   = (q >> 1) * 16;
    const int bn_row = wn + (q >> 1) * 8 + lr;
    const int b_kq   = (q & 1) * 16;

    load_stage(0, 0);

    for (int kc = 0; kc < NKCH; kc++) {
        if (kc + 1 < NKCH) { load_stage((kc + 1) & 1, kc + 1); CP_WAIT(1); }
        else               { CP_WAIT(0); }
        __syncthreads();

        const uint32_t st = sb + (kc & 1) * STG_B;
#pragma unroll
        for (int ks = 0; ks < 4; ks++) {
            uint32_t aH[4][4], aL[4][4], bH[2][4], bL[2][4];
#pragma unroll
            for (int i = 0; i < 4; i++) {
                uint32_t off = (uint32_t)(am_row + i * 16) * 128 + a_kq + ks * 32;
                uint32_t sw = off ^ ((off >> 3) & 0x70);
                LDSM4(aH[i], st + sw);
                LDSM4(aL[i], st + 16384 + sw);
            }
#pragma unroll
            for (int j2 = 0; j2 < 2; j2++) {
                uint32_t off = (uint32_t)(bn_row + j2 * 16) * 128 + b_kq + ks * 32;
                uint32_t sw = off ^ ((off >> 3) & 0x70);
                LDSM4(bH[j2], st + 32768 + sw);
                LDSM4(bL[j2], st + 49152 + sw);
            }
#pragma unroll
            for (int i = 0; i < 4; i++)
#pragma unroll
                for (int j = 0; j < 4; j++) {
                    const int jj = j >> 1, jo = (j & 1) * 2;
                    MMA16816(C[i][j], aH[i], bH[jj][jo], bH[jj][jo + 1]);
                    MMA16816(C[i][j], aH[i], bL[jj][jo], bL[jj][jo + 1]);
                    MMA16816(C[i][j], aL[i], bH[jj][jo], bH[jj][jo + 1]);
                }
        }
        __syncthreads();
    }

    const int g  = lane >> 2;
    const int tg = lane & 3;
#pragma unroll
    for (int i = 0; i < 4; i++) {
#pragma unroll
        for (int j = 0; j < 4; j++) {
            const int ncol = wn + j * 8 + tg * 2;
            const int r0 = bm + wm + i * 16 + g;
            const int r1 = r0 + 8;
            if (MODE == 0) {
                const int col = bn + ncol;
                float b0v = bias[col], b1v = bias[col + 1];
                float y00 = C[i][j][0] + b0v, y01 = C[i][j][1] + b1v;
                float y10 = C[i][j][2] + b0v, y11 = C[i][j][3] + b1v;
                float l00 = y00 - __bfloat162float(__float2bfloat16_rn(y00));
                float l01 = y01 - __bfloat162float(__float2bfloat16_rn(y01));
                float l10 = y10 - __bfloat162float(__float2bfloat16_rn(y10));
                float l11 = y11 - __bfloat162float(__float2bfloat16_rn(y11));
                *(uint32_t*)(Yh + (size_t)r0 * 1024 + col) = pbf2(y00, y01);
                *(uint32_t*)(Yh + (size_t)r1 * 1024 + col) = pbf2(y10, y11);
                *(uint32_t*)(Yl + (size_t)r0 * 1024 + col) = pbf2(l00, l01);
                *(uint32_t*)(Yl + (size_t)r1 * 1024 + col) = pbf2(l10, l11);
            } else {
                const int n = blockIdx.x * 128 + ncol;
                const int bb = n >> 6, dd = n & 63;
                float* p0 = Yf + ((size_t)bb * 1024 + r0) * 1024 + h * 64 + dd;
                float* p1 = Yf + ((size_t)bb * 1024 + r1) * 1024 + h * 64 + dd;
                float2 o0 = *(float2*)p0, o1 = *(float2*)p1;
                o0.x += C[i][j][0]; o0.y += C[i][j][1];
                o1.x += C[i][j][2]; o1.y += C[i][j][3];
                *(float2*)p0 = o0;
                *(float2*)p1 = o1;
            }
        }
    }
}

// ================= tensor-core flash attention =================
// CTA: 128 q-rows x (b,h). 8 warps x 16 rows. K-tile = 64, double buffered.
#define FQH 0
#define FQL 16384
#define FST0 32768
#define FKH 0
#define FKL 8192
#define FVH 16384
#define FVL 24576
#define FSRC 32768
#define FSTG 32896
#define FSMEM (32768 + 2 * FSTG)

__global__ __launch_bounds__(256)
void flash_tc(float* __restrict__ out)
{
    char* sm = smem_raw;
    const uint32_t sb = smem_u32(sm);
    const int tid  = threadIdx.x;
    const int lane = tid & 31;
    const int w    = tid >> 5;
    const int q0 = blockIdx.x * 128;
    const int h  = blockIdx.y;
    const int b  = blockIdx.z;
    const int g  = lane >> 2;
    const int tg = lane & 3;
    const int qq = lane >> 3;
    const int lr = lane & 7;

    // ---- Q load (group 0) ----
    {
#pragma unroll
        for (int i = 0; i < 4; i++) {
            int idx = tid + i * 256;
            int row = idx >> 3, c = idx & 7;
            uint32_t off = row * 128 + c * 16;
            uint32_t sw = off ^ ((off >> 3) & 0x70);
            size_t gq = ((size_t)b * 1024 + q0 + row) * 1024 + h * 64 + c * 8;
            CP_ASYNC16(sb + FQH + sw, g_qph + gq);
            CP_ASYNC16(sb + FQL + sw, g_qpl + gq);
        }
        CP_COMMIT();
    }

    auto load_stage = [&](int s, int kt) {
        const uint32_t st = sb + FST0 + s * FSTG;
        const int k0 = kt * 64;
#pragma unroll
        for (int i = 0; i < 2; i++) {
            int idx = tid + i * 256;
            int row = idx >> 3, c = idx & 7;
            uint32_t off = row * 128 + c * 16;
            uint32_t sw = off ^ ((off >> 3) & 0x70);
            size_t gk = ((size_t)b * 1024 + k0 + row) * 1024 + h * 64 + c * 8;
            CP_ASYNC16(st + FKH + sw, g_kph + gk);
            CP_ASYNC16(st + FKL + sw, g_kpl + gk);
            CP_ASYNC16(st + FVH + sw, g_vph + gk);
            CP_ASYNC16(st + FVL + sw, g_vpl + gk);
        }
        if (tid < 4)
            CP_ASYNC16(st + FSRC + tid * 16, g_src8 + b * 1024 + k0 + tid * 16);
        CP_COMMIT();
    };

    load_stage(0, 0);

    const unsigned char t0m = g_tgt8[b * 1024 + q0 + w * 16 + g];
    const unsigned char t1m = g_tgt8[b * 1024 + q0 + w * 16 + 8 + g];

    float m0r = -3.0e38f, m1r = -3.0e38f, l0r = 0.0f, l1r = 0.0f;
    float O[8][4];
#pragma unroll
    for (int i = 0; i < 8; i++)
#pragma unroll
        for (int r = 0; r < 4; r++) O[i][r] = 0.0f;

    uint32_t aQh[4][4], aQl[4][4];

    for (int kt = 0; kt < 16; kt++) {
        if (kt + 1 < 16) { load_stage((kt + 1) & 1, kt + 1); CP_WAIT(1); }
        else             { CP_WAIT(0); }
        __syncthreads();

        if (kt == 0) {
#pragma unroll
            for (int kc = 0; kc < 4; kc++) {
                uint32_t off = (uint32_t)(w * 16 + (qq & 1) * 8 + lr) * 128 + (qq >> 1) * 16 + kc * 32;
                uint32_t sw = off ^ ((off >> 3) & 0x70);
                LDSM4(aQh[kc], sb + FQH + sw);
                LDSM4(aQl[kc], sb + FQL + sw);
            }
        }

        const uint32_t st = sb + FST0 + (kt & 1) * FSTG;
        char* stp = sm + FST0 + (kt & 1) * FSTG;

        // ---- S = Q @ K^T (split bf16, 3 passes) ----
        float C[8][4];
#pragma unroll
        for (int i = 0; i < 8; i++)
#pragma unroll
            for (int r = 0; r < 4; r++) C[i][r] = 0.0f;
#pragma unroll
        for (int ks = 0; ks < 4; ks++) {
#pragma unroll
            for (int j2 = 0; j2 < 4; j2++) {
                uint32_t bh[4], bl[4];
                uint32_t off = (uint32_t)(j2 * 16 + (qq >> 1) * 8 + lr) * 128 + (qq & 1) * 16 + ks * 32;
                uint32_t sw = off ^ ((off >> 3) & 0x70);
                LDSM4(bh, st + FKH + sw);
                LDSM4(bl, st + FKL + sw);
                MMA16816(C[j2 * 2],     aQh[ks], bh[0], bh[1]);
                MMA16816(C[j2 * 2],     aQh[ks], bl[0], bl[1]);
                MMA16816(C[j2 * 2],     aQl[ks], bh[0], bh[1]);
                MMA16816(C[j2 * 2 + 1], aQh[ks], bh[2], bh[3]);
                MMA16816(C[j2 * 2 + 1], aQh[ks], bl[2], bl[3]);
                MMA16816(C[j2 * 2 + 1], aQl[ks], bh[2], bh[3]);
            }
        }

        // ---- mask + online softmax ----
        float mx0 = -3.0e38f, mx1 = -3.0e38f;
#pragma unroll
        for (int nt = 0; nt < 8; nt++) {
            unsigned char s0 = *(unsigned char*)(stp + FSRC + nt * 8 + tg * 2);
            unsigned char s1 = *(unsigned char*)(stp + FSRC + nt * 8 + tg * 2 + 1);
            C[nt][0] = (t0m && s0) ? C[nt][0] * SCALE : NEGV;
            C[nt][1] = (t0m && s1) ? C[nt][1] * SCALE : NEGV;
            C[nt][2] = (t1m && s0) ? C[nt][2] * SCALE : NEGV;
            C[nt][3] = (t1m && s1) ? C[nt][3] * SCALE : NEGV;
            mx0 = fmaxf(mx0, fmaxf(C[nt][0], C[nt][1]));
            mx1 = fmaxf(mx1, fmaxf(C[nt][2], C[nt][3]));
        }
        mx0 = fmaxf(mx0, __shfl_xor_sync(0xFFFFFFFF, mx0, 1));
        mx0 = fmaxf(mx0, __shfl_xor_sync(0xFFFFFFFF, mx0, 2));
        mx1 = fmaxf(mx1, __shfl_xor_sync(0xFFFFFFFF, mx1, 1));
        mx1 = fmaxf(mx1, __shfl_xor_sync(0xFFFFFFFF, mx1, 2));

        float mn0 = fmaxf(m0r, mx0), mn1 = fmaxf(m1r, mx1);
        float f0 = __expf(m0r - mn0), f1 = __expf(m1r - mn1);
        m0r = mn0; m1r = mn1;

        float s0 = 0.0f, s1 = 0.0f;
#pragma unroll
        for (int nt = 0; nt < 8; nt++) {
            C[nt][0] = __expf(C[nt][0] - mn0);
            C[nt][1] = __expf(C[nt][1] - mn0);
            C[nt][2] = __expf(C[nt][2] - mn1);
            C[nt][3] = __expf(C[nt][3] - mn1);
            s0 += C[nt][0] + C[nt][1];
            s1 += C[nt][2] + C[nt][3];
        }
        s0 += __shfl_xor_sync(0xFFFFFFFF, s0, 1);
        s0 += __shfl_xor_sync(0xFFFFFFFF, s0, 2);
        s1 += __shfl_xor_sync(0xFFFFFFFF, s1, 1);
        s1 += __shfl_xor_sync(0xFFFFFFFF, s1, 2);
        l0r = l0r * f0 + s0;
        l1r = l1r * f1 + s1;

#pragma unroll
        for (int nt = 0; nt < 8; nt++) {
            O[nt][0] *= f0; O[nt][1] *= f0;
            O[nt][2] *= f1; O[nt][3] *= f1;
        }

        // ---- pack P into A-frags (hi/lo) ----
        uint32_t aPh[4][4], aPl[4][4];
#pragma unroll
        for (int kc = 0; kc < 4; kc++) {
            const int n0 = kc * 2, n1 = kc * 2 + 1;
            aPh[kc][0] = pbf2(C[n0][0], C[n0][1]);
            aPh[kc][1] = pbf2(C[n0][2], C[n0][3]);
            aPh[kc][2] = pbf2(C[n1][0], C[n1][1]);
            aPh[kc][3] = pbf2(C[n1][2], C[n1][3]);
            float l00 = C[n0][0] - __bfloat162float(__float2bfloat16_rn(C[n0][0]));
            float l01 = C[n0][1] - __bfloat162float(__float2bfloat16_rn(C[n0][1]));
            float l02 = C[n0][2] - __bfloat162float(__float2bfloat16_rn(C[n0][2]));
            float l03 = C[n0][3] - __bfloat162float(__float2bfloat16_rn(C[n0][3]));
            float l10 = C[n1][0] - __bfloat162float(__float2bfloat16_rn(C[n1][0]));
            float l11 = C[n1][1] - __bfloat162float(__float2bfloat16_rn(C[n1][1]));
            float l12 = C[n1][2] - __bfloat162float(__float2bfloat16_rn(C[n1][2]));
            float l13 = C[n1][3] - __bfloat162float(__float2bfloat16_rn(C[n1][3]));
            aPl[kc][0] = pbf2(l00, l01);
            aPl[kc][1] = pbf2(l02, l03);
            aPl[kc][2] = pbf2(l10, l11);
            aPl[kc][3] = pbf2(l12, l13);
        }

        // ---- O += P @ V (split, 3 passes; V via ldmatrix.trans) ----
#pragma unroll
        for (int kc = 0; kc < 4; kc++) {
#pragma unroll
            for (int nd = 0; nd < 4; nd++) {
                uint32_t vh[4], vl[4];
                uint32_t off = (uint32_t)(kc * 16 + (qq & 1) * 8 + lr) * 128 +
                               (nd * 16 + (qq >> 1) * 8) * 2;
                uint32_t sw = off ^ ((off >> 3) & 0x70);
                LDSM4T(vh, st + FVH + sw);
                LDSM4T(vl, st + FVL + sw);
                MMA16816(O[nd * 2],     aPh[kc], vh[0], vh[1]);
                MMA16816(O[nd * 2],     aPl[kc], vh[0], vh[1]);
                MMA16816(O[nd * 2],     aPh[kc], vl[0], vl[1]);
                MMA16816(O[nd * 2 + 1], aPh[kc], vh[2], vh[3]);
                MMA16816(O[nd * 2 + 1], aPl[kc], vh[2], vh[3]);
                MMA16816(O[nd * 2 + 1], aPh[kc], vl[2], vl[3]);
            }
        }
        __syncthreads();
    }

    // ---- epilogue ----
    const float il0 = 1.0f / l0r, il1 = 1.0f / l1r;
    const int r0 = q0 + w * 16 + g;
    const int r1 = r0 + 8;
#pragma unroll
    for (int nt = 0; nt < 8; nt++) {
        const int col = h * 64 + nt * 8 + tg * 2;
        float2 w0 = make_float2(O[nt][0] * il0, O[nt][1] * il0);
        float2 w1 = make_float2(O[nt][2] * il1, O[nt][3] * il1);
        *(float2*)(out + ((size_t)b * 1024 + r0) * 1024 + col) = w0;
        *(float2*)(out + ((size_t)b * 1024 + r1) * 1024 + col) = w1;
    }
}

// ================= kernel_launch =================
extern "C" void kernel_launch(void* const* d_in, const int* in_sizes, int n_in,
                              void* d_out, int out_size)
{
    const float* q    = (const float*)d_in[0];
    const float* k    = (const float*)d_in[1];
    const float* v    = (const float*)d_in[2];
    const float* beta = (const float*)d_in[3];
    const unsigned char* srcm = (const unsigned char*)d_in[4];
    const unsigned char* tgtm = (const unsigned char*)d_in[5];
    const float* Wq = (const float*)d_in[6];
    const float* bq = (const float*)d_in[7];
    const float* Wk = (const float*)d_in[8];
    const float* bk = (const float*)d_in[9];
    const float* Wv = (const float*)d_in[10];
    const float* bv = (const float*)d_in[11];
    float* out = (float*)d_out;

    void *qph, *qpl, *kph, *kpl, *vph, *vpl, *ah, *al, *bh, *bl, *vth, *vtl;
    cudaGetSymbolAddress(&qph, g_qph);
    cudaGetSymbolAddress(&qpl, g_qpl);
    cudaGetSymbolAddress(&kph, g_kph);
    cudaGetSymbolAddress(&kpl, g_kpl);
    cudaGetSymbolAddress(&vph, g_vph);
    cudaGetSymbolAddress(&vpl, g_vpl);
    cudaGetSymbolAddress(&ah, g_ah);
    cudaGetSymbolAddress(&al, g_al);
    cudaGetSymbolAddress(&bh, g_bh);
    cudaGetSymbolAddress(&bl, g_bl);
    cudaGetSymbolAddress(&vth, g_vth);
    cudaGetSymbolAddress(&vtl, g_vtl);

    cudaFuncSetAttribute(gemm_mma<0>, cudaFuncAttributeMaxDynamicSharedMemorySize, GSMEM_TOTAL);
    cudaFuncSetAttribute(gemm_mma<1>, cudaFuncAttributeMaxDynamicSharedMemorySize, GSMEM_TOTAL);
    cudaFuncSetAttribute(flash_tc, cudaFuncAttributeMaxDynamicSharedMemorySize, FSMEM);

    mask_convert<<<1, 1024>>>(srcm, Bb * TK, 0);
    mask_convert<<<1, 1024>>>(tgtm, Bb * TQ, 1);

    const int n4_act  = (MROWS * DIMX) / 4;
    const int n4_w    = (DIMX * DIMX) / 4;
    const int n4_beta = (NH * TQ * TK) / 4;
    dim3 pgrid(8, 64);

    // Q projection -> bf16 hi/lo
    conv_split<<<(n4_act + 255) / 256, 256>>>((const float4*)q, (__nv_bfloat16*)ah, (__nv_bfloat16*)al, n4_act);
    conv_split<<<(n4_w + 255) / 256, 256>>>((const float4*)Wq, (__nv_bfloat16*)bh, (__nv_bfloat16*)bl, n4_w);
    gemm_mma<0><<<pgrid, 256, GSMEM_TOTAL>>>((const __nv_bfloat16*)ah, (const __nv_bfloat16*)al,
                                             (const __nv_bfloat16*)bh, (const __nv_bfloat16*)bl,
                                             bq, (__nv_bfloat16*)qph, (__nv_bfloat16*)qpl, nullptr);
    // K projection
    conv_split<<<(n4_act + 255) / 256, 256>>>((const float4*)k, (__nv_bfloat16*)ah, (__nv_bfloat16*)al, n4_act);
    conv_split<<<(n4_w + 255) / 256, 256>>>((const float4*)Wk, (__nv_bfloat16*)bh, (__nv_bfloat16*)bl, n4_w);
    gemm_mma<0><<<pgrid, 256, GSMEM_TOTAL>>>((const __nv_bfloat16*)ah, (const __nv_bfloat16*)al,
                                             (const __nv_bfloat16*)bh, (const __nv_bfloat16*)bl,
                                             bk, (__nv_bfloat16*)kph, (__nv_bfloat16*)kpl, nullptr);
    // V projection
    conv_split<<<(n4_act + 255) / 256, 256>>>((const float4*)v, (__nv_bfloat16*)ah, (__nv_bfloat16*)al, n4_act);
    conv_split<<<(n4_w + 255) / 256, 256>>>((const float4*)Wv, (__nv_bfloat16*)bh, (__nv_bfloat16*)bl, n4_w);
    gemm_mma<0><<<pgrid, 256, GSMEM_TOTAL>>>((const __nv_bfloat16*)ah, (const __nv_bfloat16*)al,
                                             (const __nv_bfloat16*)bh, (const __nv_bfloat16*)bl,
                                             bv, (__nv_bfloat16*)vph, (__nv_bfloat16*)vpl, nullptr);

    // tensor-core flash attention (writes out)
    flash_tc<<<dim3(TQ / 128, NH, Bb), 256, FSMEM>>>(out);

    // beta @ V accumulated into out
    vtrans<<<dim3(16, 16, 8), 256>>>();
    conv_split<<<(n4_beta + 255) / 256, 256>>>((const float4*)beta, (__nv_bfloat16*)ah, (__nv_bfloat16*)al, n4_beta);
    gemm_mma<1><<<dim3(4, 8, 16), 256, GSMEM_TOTAL>>>((const __nv_bfloat16*)ah, (const __nv_bfloat16*)al,
                                                      (const __nv_bfloat16*)vth, (const __nv_bfloat16*)vtl,
                                                      nullptr, nullptr, nullptr, out);
}

// round 5
// speedup vs baseline: 3.4437x; 1.0617x over previous
#include <cuda_runtime.h>
#include <cuda_bf16.h>
#include <math.h>
#include <stdint.h>

// Problem constants
#define Bb    8
#define TQ    1024
#define TK    1024
#define DIMX  1024
#define NH    16
#define HD    64
#define SCALE 0.03125f
#define NEGV  -1.0e9f
#define MROWS (Bb * TQ)  /* 8192 */
#define SC2L  (0.03125f * 1.44269504088896f)  /* scale * log2(e) */

// ================= PTX helpers (baseline ISA only) =================
__device__ __forceinline__ uint32_t smem_u32(const void* p) {
    uint32_t a;
    asm("{ .reg .u64 t; cvta.to.shared.u64 t, %1; cvt.u32.u64 %0, t; }"
        : "=r"(a) : "l"(p));
    return a;
}
#define CP_ASYNC16(dst_u32, src_ptr) \
    asm volatile("cp.async.cg.shared.global [%0], [%1], 16;" \
        :: "r"(dst_u32), "l"(src_ptr))
#define CP_COMMIT() asm volatile("cp.async.commit_group;" ::: "memory")
#define CP_WAIT(n)  asm volatile("cp.async.wait_group %0;" :: "n"(n) : "memory")

#define LDSM4(r, addr) \
    asm volatile("ldmatrix.sync.aligned.m8n8.x4.shared.b16 {%0,%1,%2,%3}, [%4];" \
        : "=r"((r)[0]), "=r"((r)[1]), "=r"((r)[2]), "=r"((r)[3]) : "r"(addr))
#define LDSM4T(r, addr) \
    asm volatile("ldmatrix.sync.aligned.m8n8.x4.trans.shared.b16 {%0,%1,%2,%3}, [%4];" \
        : "=r"((r)[0]), "=r"((r)[1]), "=r"((r)[2]), "=r"((r)[3]) : "r"(addr))

#define MMA16816(c, a, b0, b1) \
    asm volatile("mma.sync.aligned.m16n8k16.row.col.f32.bf16.bf16.f32 " \
        "{%0,%1,%2,%3}, {%4,%5,%6,%7}, {%8,%9}, {%0,%1,%2,%3};" \
        : "+f"((c)[0]), "+f"((c)[1]), "+f"((c)[2]), "+f"((c)[3]) \
        : "r"((a)[0]), "r"((a)[1]), "r"((a)[2]), "r"((a)[3]), "r"(b0), "r"(b1))

__device__ __forceinline__ uint32_t pbf2(float lo, float hi) {
    uint32_t d;
    asm("cvt.rn.bf16x2.f32 %0, %1, %2;" : "=r"(d) : "f"(hi), "f"(lo));
    return d;
}
__device__ __forceinline__ float ex2f(float x) {
    float y;
    asm("ex2.approx.ftz.f32 %0, %1;" : "=f"(y) : "f"(x));
    return y;
}

// ================= scratch (device globals, 16B aligned) =================
__device__ __align__(16) __nv_bfloat16 g_qph[(size_t)MROWS * DIMX];
__device__ __align__(16) __nv_bfloat16 g_qpl[(size_t)MROWS * DIMX];
__device__ __align__(16) __nv_bfloat16 g_kph[(size_t)MROWS * DIMX];
__device__ __align__(16) __nv_bfloat16 g_kpl[(size_t)MROWS * DIMX];
__device__ __align__(16) __nv_bfloat16 g_vph[(size_t)MROWS * DIMX];
__device__ __align__(16) __nv_bfloat16 g_vpl[(size_t)MROWS * DIMX];
__device__ __align__(16) __nv_bfloat16 g_ah[(size_t)24 * 1024 * 1024];  // acts q|k|v, or beta
__device__ __align__(16) __nv_bfloat16 g_al[(size_t)24 * 1024 * 1024];
__device__ __align__(16) __nv_bfloat16 g_bh[(size_t)3 * 1024 * 1024];   // weights q|k|v
__device__ __align__(16) __nv_bfloat16 g_bl[(size_t)3 * 1024 * 1024];
__device__ unsigned char g_src8[Bb * TK];
__device__ unsigned char g_tgt8[Bb * TQ];

// ================= mask canonicalization =================
__global__ void mask_convert(const unsigned char* __restrict__ raw, int n, int which)
{
    __shared__ int has3F, oddNZ;
    if (threadIdx.x == 0) { has3F = 0; oddNZ = 0; }
    __syncthreads();
    int lf = 0, lo = 0;
    for (int i = threadIdx.x; i < n; i += blockDim.x) {
        unsigned char c = raw[i];
        if (c == 0x3F) lf = 1;
        if ((i & 3) && c) lo = 1;
    }
    if (lf) atomicOr(&has3F, 1);
    if (lo) atomicOr(&oddNZ, 1);
    __syncthreads();
    unsigned char* out = which ? g_tgt8 : g_src8;
    int mode = has3F ? 2 : (oddNZ ? 0 : 1);
    for (int i = threadIdx.x; i < n; i += blockDim.x) {
        unsigned char v;
        if (mode == 2)      v = (((const float*)raw)[i] != 0.0f) ? 1 : 0;
        else if (mode == 1) v = (((const int*)raw)[i]   != 0)    ? 1 : 0;
        else                v = (raw[i] != 0) ? 1 : 0;
        out[i] = v;
    }
}

// ================= fp32 -> (bf16 hi, bf16 lo) split =================
__global__ __launch_bounds__(256)
void conv_split(const float4* __restrict__ x, __nv_bfloat16* __restrict__ hi,
                __nv_bfloat16* __restrict__ lo, int n4)
{
    int i = blockIdx.x * 256 + threadIdx.x;
    if (i >= n4) return;
    float4 f = x[i];
    __nv_bfloat16 h0 = __float2bfloat16_rn(f.x);
    __nv_bfloat16 h1 = __float2bfloat16_rn(f.y);
    __nv_bfloat16 h2 = __float2bfloat16_rn(f.z);
    __nv_bfloat16 h3 = __float2bfloat16_rn(f.w);
    __nv_bfloat16 l0 = __float2bfloat16_rn(f.x - __bfloat162float(h0));
    __nv_bfloat16 l1 = __float2bfloat16_rn(f.y - __bfloat162float(h1));
    __nv_bfloat16 l2 = __float2bfloat16_rn(f.z - __bfloat162float(h2));
    __nv_bfloat16 l3 = __float2bfloat16_rn(f.w - __bfloat162float(h3));
    __nv_bfloat162* Hp = (__nv_bfloat162*)(hi + 4 * (size_t)i);
    __nv_bfloat162* Lp = (__nv_bfloat162*)(lo + 4 * (size_t)i);
    Hp[0] = __halves2bfloat162(h0, h1);
    Hp[1] = __halves2bfloat162(h2, h3);
    Lp[0] = __halves2bfloat162(l0, l1);
    Lp[1] = __halves2bfloat162(l2, l3);
}

// ================= mma.sync split-bf16 GEMM =================
// MODE 0 (fused QKV): seg = bx>>3 picks {A,W,bias,out}; Y = A @ W^T + bias -> bf16 hi/lo
// MODE 1 (beta@V):    out[b, bm+q, h*64+d] += beta_h @ V (V natural [k][d] via ldmatrix.trans)
#define NKCH 16
#define STG_B 65536
#define GSMEM_TOTAL (2 * STG_B)

extern __shared__ char smem_raw[];

template <int MODE>
__global__ __launch_bounds__(256)
void gemm_mma(const float* __restrict__ bias0, const float* __restrict__ bias1,
              const float* __restrict__ bias2, float* __restrict__ Yf)
{
    const uint32_t sb = smem_u32(smem_raw);
    const int tid  = threadIdx.x;
    const int lane = tid & 31;
    const int wid  = tid >> 5;
    const int wm = (wid >> 2) * 64;
    const int wn = (wid & 3) * 32;

    int bm, bn = 0, h = 0, b0 = 0, seg = 0;
    size_t arow0;
    const __nv_bfloat16 *Ahg, *Alg, *Bhg = nullptr, *Blg = nullptr;
    const float* bias = nullptr;
    __nv_bfloat16 *Yh = nullptr, *Yl = nullptr;
    if (MODE == 0) {
        seg = blockIdx.x >> 3;
        bn = (blockIdx.x & 7) * 128;
        bm = blockIdx.y * 128;
        arow0 = (size_t)bm;
        Ahg = g_ah + (size_t)seg * 8 * 1024 * 1024;
        Alg = g_al + (size_t)seg * 8 * 1024 * 1024;
        Bhg = g_bh + (size_t)seg * 1024 * 1024;
        Blg = g_bl + (size_t)seg * 1024 * 1024;
        bias = (seg == 0) ? bias0 : (seg == 1) ? bias1 : bias2;
        Yh = (seg == 0) ? g_qph : (seg == 1) ? g_kph : g_vph;
        Yl = (seg == 0) ? g_qpl : (seg == 1) ? g_kpl : g_vpl;
    } else {
        b0 = blockIdx.x * 2; bm = blockIdx.y * 128; h = blockIdx.z;
        arow0 = (size_t)h * 1024 + bm;
        Ahg = g_ah; Alg = g_al;
    }

    float C[4][4][4];
#pragma unroll
    for (int i = 0; i < 4; i++)
#pragma unroll
        for (int j = 0; j < 4; j++)
#pragma unroll
            for (int r = 0; r < 4; r++) C[i][j][r] = 0.0f;

    auto load_stage = [&](int s, int kc) {
        const uint32_t st = sb + s * STG_B;
        const int koff = kc * 64;
        // A tile: 128 rows x 64 k (128B rows), hi+lo
#pragma unroll
        for (int i = 0; i < 4; i++) {
            int idx = tid + i * 256;
            int row = idx >> 3, c = idx & 7;
            uint32_t off = row * 128 + c * 16;
            uint32_t sw = off ^ ((off >> 3) & 0x70);
            size_t gA = (arow0 + row) * 1024 + koff + c * 8;
            CP_ASYNC16(st + sw,          Ahg + gA);
            CP_ASYNC16(st + 16384 + sw,  Alg + gA);
        }
        if (MODE == 0) {
            // B: weights k-major, 128 rows x 64 k
#pragma unroll
            for (int i = 0; i < 4; i++) {
                int idx = tid + i * 256;
                int row = idx >> 3, c = idx & 7;
                uint32_t off = row * 128 + c * 16;
                uint32_t sw = off ^ ((off >> 3) & 0x70);
                size_t gB = (size_t)(bn + row) * 1024 + koff + c * 8;
                CP_ASYNC16(st + 32768 + sw,  Bhg + gB);
                CP_ASYNC16(st + 49152 + sw,  Blg + gB);
            }
        } else {
            // V natural [k][d]: 2 batch-halves, each 64 k-rows x 64 d (128B rows)
#pragma unroll
            for (int i = 0; i < 4; i++) {
                int idx = tid + i * 256;
                int half = idx >> 9, row = (idx >> 3) & 63, c = idx & 7;
                uint32_t off = row * 128 + c * 16;
                uint32_t sw = off ^ ((off >> 3) & 0x70);
                size_t gV = ((size_t)(b0 + half) * 1024 + koff + row) * 1024 + h * 64 + c * 8;
                CP_ASYNC16(st + 32768 + half * 8192 + sw, g_vph + gV);
                CP_ASYNC16(st + 49152 + half * 8192 + sw, g_vpl + gV);
            }
        }
        CP_COMMIT();
    };

    const int q  = lane >> 3;
    const int lr = lane & 7;
    const int am_row = wm + (q & 1) * 8 + lr;
    const int a_kq   = (q >> 1) * 16;
    const int bn_row = wn + (q >> 1) * 8 + lr;   // MODE 0
    const int b_kq   = (q & 1) * 16;

    load_stage(0, 0);

    for (int kc = 0; kc < NKCH; kc++) {
        if (kc + 1 < NKCH) { load_stage((kc + 1) & 1, kc + 1); CP_WAIT(1); }
        else               { CP_WAIT(0); }
        __syncthreads();

        const uint32_t st = sb + (kc & 1) * STG_B;
#pragma unroll
        for (int ks = 0; ks < 4; ks++) {
            uint32_t aH[4][4], aL[4][4], bH[2][4], bL[2][4];
#pragma unroll
            for (int i = 0; i < 4; i++) {
                uint32_t off = (uint32_t)(am_row + i * 16) * 128 + a_kq + ks * 32;
                uint32_t sw = off ^ ((off >> 3) & 0x70);
                LDSM4(aH[i], st + sw);
                LDSM4(aL[i], st + 16384 + sw);
            }
#pragma unroll
            for (int j2 = 0; j2 < 2; j2++) {
                if (MODE == 0) {
                    uint32_t off = (uint32_t)(bn_row + j2 * 16) * 128 + b_kq + ks * 32;
                    uint32_t sw = off ^ ((off >> 3) & 0x70);
                    LDSM4(bH[j2], st + 32768 + sw);
                    LDSM4(bL[j2], st + 49152 + sw);
                } else {
                    const int n16 = wn + j2 * 16;
                    const int half = n16 >> 6, d0 = n16 & 63;
                    uint32_t off = (uint32_t)(ks * 16 + (q & 1) * 8 + lr) * 128 +
                                   (d0 + (q >> 1) * 8) * 2;
                    uint32_t sw = off ^ ((off >> 3) & 0x70);
                    LDSM4T(bH[j2], st + 32768 + half * 8192 + sw);
                    LDSM4T(bL[j2], st + 49152 + half * 8192 + sw);
                }
            }
#pragma unroll
            for (int i = 0; i < 4; i++)
#pragma unroll
                for (int j = 0; j < 4; j++) {
                    const int jj = j >> 1, jo = (j & 1) * 2;
                    MMA16816(C[i][j], aH[i], bH[jj][jo], bH[jj][jo + 1]);
                    MMA16816(C[i][j], aH[i], bL[jj][jo], bL[jj][jo + 1]);
                    MMA16816(C[i][j], aL[i], bH[jj][jo], bH[jj][jo + 1]);
                }
        }
        __syncthreads();
    }

    const int g  = lane >> 2;
    const int tg = lane & 3;
#pragma unroll
    for (int i = 0; i < 4; i++) {
#pragma unroll
        for (int j = 0; j < 4; j++) {
            const int ncol = wn + j * 8 + tg * 2;
            const int r0 = bm + wm + i * 16 + g;
            const int r1 = r0 + 8;
            if (MODE == 0) {
                const int col = bn + ncol;
                float b0v = bias[col], b1v = bias[col + 1];
                float y00 = C[i][j][0] + b0v, y01 = C[i][j][1] + b1v;
                float y10 = C[i][j][2] + b0v, y11 = C[i][j][3] + b1v;
                float l00 = y00 - __bfloat162float(__float2bfloat16_rn(y00));
                float l01 = y01 - __bfloat162float(__float2bfloat16_rn(y01));
                float l10 = y10 - __bfloat162float(__float2bfloat16_rn(y10));
                float l11 = y11 - __bfloat162float(__float2bfloat16_rn(y11));
                *(uint32_t*)(Yh + (size_t)r0 * 1024 + col) = pbf2(y00, y01);
                *(uint32_t*)(Yh + (size_t)r1 * 1024 + col) = pbf2(y10, y11);
                *(uint32_t*)(Yl + (size_t)r0 * 1024 + col) = pbf2(l00, l01);
                *(uint32_t*)(Yl + (size_t)r1 * 1024 + col) = pbf2(l10, l11);
            } else {
                const int n = blockIdx.x * 128 + ncol;
                const int bb = n >> 6, dd = n & 63;
                float* p0 = Yf + ((size_t)bb * 1024 + r0) * 1024 + h * 64 + dd;
                float* p1 = Yf + ((size_t)bb * 1024 + r1) * 1024 + h * 64 + dd;
                float2 o0 = *(float2*)p0, o1 = *(float2*)p1;
                o0.x += C[i][j][0]; o0.y += C[i][j][1];
                o1.x += C[i][j][2]; o1.y += C[i][j][3];
                *(float2*)p0 = o0;
                *(float2*)p1 = o1;
            }
        }
    }
}

// ================= tensor-core flash attention (exp2 domain) =================
#define FQH 0
#define FQL 16384
#define FST0 32768
#define FKH 0
#define FKL 8192
#define FVH 16384
#define FVL 24576
#define FSRC 32768
#define FSTG 32896
#define FSMEM (32768 + 2 * FSTG)

__global__ __launch_bounds__(256)
void flash_tc(float* __restrict__ out)
{
    char* sm = smem_raw;
    const uint32_t sb = smem_u32(sm);
    const int tid  = threadIdx.x;
    const int lane = tid & 31;
    const int w    = tid >> 5;
    const int q0 = blockIdx.x * 128;
    const int h  = blockIdx.y;
    const int b  = blockIdx.z;
    const int g  = lane >> 2;
    const int tg = lane & 3;
    const int qq = lane >> 3;
    const int lr = lane & 7;

    {
#pragma unroll
        for (int i = 0; i < 4; i++) {
            int idx = tid + i * 256;
            int row = idx >> 3, c = idx & 7;
            uint32_t off = row * 128 + c * 16;
            uint32_t sw = off ^ ((off >> 3) & 0x70);
            size_t gq = ((size_t)b * 1024 + q0 + row) * 1024 + h * 64 + c * 8;
            CP_ASYNC16(sb + FQH + sw, g_qph + gq);
            CP_ASYNC16(sb + FQL + sw, g_qpl + gq);
        }
        CP_COMMIT();
    }

    auto load_stage = [&](int s, int kt) {
        const uint32_t st = sb + FST0 + s * FSTG;
        const int k0 = kt * 64;
#pragma unroll
        for (int i = 0; i < 2; i++) {
            int idx = tid + i * 256;
            int row = idx >> 3, c = idx & 7;
            uint32_t off = row * 128 + c * 16;
            uint32_t sw = off ^ ((off >> 3) & 0x70);
            size_t gk = ((size_t)b * 1024 + k0 + row) * 1024 + h * 64 + c * 8;
            CP_ASYNC16(st + FKH + sw, g_kph + gk);
            CP_ASYNC16(st + FKL + sw, g_kpl + gk);
            CP_ASYNC16(st + FVH + sw, g_vph + gk);
            CP_ASYNC16(st + FVL + sw, g_vpl + gk);
        }
        if (tid < 4)
            CP_ASYNC16(st + FSRC + tid * 16, g_src8 + b * 1024 + k0 + tid * 16);
        CP_COMMIT();
    };

    load_stage(0, 0);

    const unsigned char t0m = g_tgt8[b * 1024 + q0 + w * 16 + g];
    const unsigned char t1m = g_tgt8[b * 1024 + q0 + w * 16 + 8 + g];

    float m0r = -3.0e38f, m1r = -3.0e38f, l0r = 0.0f, l1r = 0.0f;
    float O[8][4];
#pragma unroll
    for (int i = 0; i < 8; i++)
#pragma unroll
        for (int r = 0; r < 4; r++) O[i][r] = 0.0f;

    uint32_t aQh[4][4], aQl[4][4];

    for (int kt = 0; kt < 16; kt++) {
        if (kt + 1 < 16) { load_stage((kt + 1) & 1, kt + 1); CP_WAIT(1); }
        else             { CP_WAIT(0); }
        __syncthreads();

        if (kt == 0) {
#pragma unroll
            for (int kc = 0; kc < 4; kc++) {
                uint32_t off = (uint32_t)(w * 16 + (qq & 1) * 8 + lr) * 128 + (qq >> 1) * 16 + kc * 32;
                uint32_t sw = off ^ ((off >> 3) & 0x70);
                LDSM4(aQh[kc], sb + FQH + sw);
                LDSM4(aQl[kc], sb + FQL + sw);
            }
        }

        const uint32_t st = sb + FST0 + (kt & 1) * FSTG;
        char* stp = sm + FST0 + (kt & 1) * FSTG;

        // ---- S = Q @ K^T ----
        float C[8][4];
#pragma unroll
        for (int i = 0; i < 8; i++)
#pragma unroll
            for (int r = 0; r < 4; r++) C[i][r] = 0.0f;
#pragma unroll
        for (int ks = 0; ks < 4; ks++) {
#pragma unroll
            for (int j2 = 0; j2 < 4; j2++) {
                uint32_t bh[4], bl[4];
                uint32_t off = (uint32_t)(j2 * 16 + (qq >> 1) * 8 + lr) * 128 + (qq & 1) * 16 + ks * 32;
                uint32_t sw = off ^ ((off >> 3) & 0x70);
                LDSM4(bh, st + FKH + sw);
                LDSM4(bl, st + FKL + sw);
                MMA16816(C[j2 * 2],     aQh[ks], bh[0], bh[1]);
                MMA16816(C[j2 * 2],     aQh[ks], bl[0], bl[1]);
                MMA16816(C[j2 * 2],     aQl[ks], bh[0], bh[1]);
                MMA16816(C[j2 * 2 + 1], aQh[ks], bh[2], bh[3]);
                MMA16816(C[j2 * 2 + 1], aQh[ks], bl[2], bl[3]);
                MMA16816(C[j2 * 2 + 1], aQl[ks], bh[2], bh[3]);
            }
        }

        // ---- mask + online softmax (log2 domain) ----
        float mx0 = -3.0e38f, mx1 = -3.0e38f;
#pragma unroll
        for (int nt = 0; nt < 8; nt++) {
            unsigned char s0 = *(unsigned char*)(stp + FSRC + nt * 8 + tg * 2);
            unsigned char s1 = *(unsigned char*)(stp + FSRC + nt * 8 + tg * 2 + 1);
            C[nt][0] = (t0m && s0) ? C[nt][0] * SC2L : NEGV;
            C[nt][1] = (t0m && s1) ? C[nt][1] * SC2L : NEGV;
            C[nt][2] = (t1m && s0) ? C[nt][2] * SC2L : NEGV;
            C[nt][3] = (t1m && s1) ? C[nt][3] * SC2L : NEGV;
            mx0 = fmaxf(mx0, fmaxf(C[nt][0], C[nt][1]));
            mx1 = fmaxf(mx1, fmaxf(C[nt][2], C[nt][3]));
        }
        mx0 = fmaxf(mx0, __shfl_xor_sync(0xFFFFFFFF, mx0, 1));
        mx0 = fmaxf(mx0, __shfl_xor_sync(0xFFFFFFFF, mx0, 2));
        mx1 = fmaxf(mx1, __shfl_xor_sync(0xFFFFFFFF, mx1, 1));
        mx1 = fmaxf(mx1, __shfl_xor_sync(0xFFFFFFFF, mx1, 2));

        float mn0 = fmaxf(m0r, mx0), mn1 = fmaxf(m1r, mx1);
        float f0 = ex2f(m0r - mn0), f1 = ex2f(m1r - mn1);
        m0r = mn0; m1r = mn1;

        float s0 = 0.0f, s1 = 0.0f;
#pragma unroll
        for (int nt = 0; nt < 8; nt++) {
            C[nt][0] = ex2f(C[nt][0] - mn0);
            C[nt][1] = ex2f(C[nt][1] - mn0);
            C[nt][2] = ex2f(C[nt][2] - mn1);
            C[nt][3] = ex2f(C[nt][3] - mn1);
            s0 += C[nt][0] + C[nt][1];
            s1 += C[nt][2] + C[nt][3];
        }
        s0 += __shfl_xor_sync(0xFFFFFFFF, s0, 1);
        s0 += __shfl_xor_sync(0xFFFFFFFF, s0, 2);
        s1 += __shfl_xor_sync(0xFFFFFFFF, s1, 1);
        s1 += __shfl_xor_sync(0xFFFFFFFF, s1, 2);
        l0r = l0r * f0 + s0;
        l1r = l1r * f1 + s1;

#pragma unroll
        for (int nt = 0; nt < 8; nt++) {
            O[nt][0] *= f0; O[nt][1] *= f0;
            O[nt][2] *= f1; O[nt][3] *= f1;
        }

        // ---- pack P into A-frags (hi/lo) ----
        uint32_t aPh[4][4], aPl[4][4];
#pragma unroll
        for (int kc = 0; kc < 4; kc++) {
            const int n0 = kc * 2, n1 = kc * 2 + 1;
            aPh[kc][0] = pbf2(C[n0][0], C[n0][1]);
            aPh[kc][1] = pbf2(C[n0][2], C[n0][3]);
            aPh[kc][2] = pbf2(C[n1][0], C[n1][1]);
            aPh[kc][3] = pbf2(C[n1][2], C[n1][3]);
            float l00 = C[n0][0] - __bfloat162float(__float2bfloat16_rn(C[n0][0]));
            float l01 = C[n0][1] - __bfloat162float(__float2bfloat16_rn(C[n0][1]));
            float l02 = C[n0][2] - __bfloat162float(__float2bfloat16_rn(C[n0][2]));
            float l03 = C[n0][3] - __bfloat162float(__float2bfloat16_rn(C[n0][3]));
            float l10 = C[n1][0] - __bfloat162float(__float2bfloat16_rn(C[n1][0]));
            float l11 = C[n1][1] - __bfloat162float(__float2bfloat16_rn(C[n1][1]));
            float l12 = C[n1][2] - __bfloat162float(__float2bfloat16_rn(C[n1][2]));
            float l13 = C[n1][3] - __bfloat162float(__float2bfloat16_rn(C[n1][3]));
            aPl[kc][0] = pbf2(l00, l01);
            aPl[kc][1] = pbf2(l02, l03);
            aPl[kc][2] = pbf2(l10, l11);
            aPl[kc][3] = pbf2(l12, l13);
        }

        // ---- O += P @ V ----
#pragma unroll
        for (int kc = 0; kc < 4; kc++) {
#pragma unroll
            for (int nd = 0; nd < 4; nd++) {
                uint32_t vh[4], vl[4];
                uint32_t off = (uint32_t)(kc * 16 + (qq & 1) * 8 + lr) * 128 +
                               (nd * 16 + (qq >> 1) * 8) * 2;
                uint32_t sw = off ^ ((off >> 3) & 0x70);
                LDSM4T(vh, st + FVH + sw);
                LDSM4T(vl, st + FVL + sw);
                MMA16816(O[nd * 2],     aPh[kc], vh[0], vh[1]);
                MMA16816(O[nd * 2],     aPl[kc], vh[0], vh[1]);
                MMA16816(O[nd * 2],     aPh[kc], vl[0], vl[1]);
                MMA16816(O[nd * 2 + 1], aPh[kc], vh[2], vh[3]);
                MMA16816(O[nd * 2 + 1], aPl[kc], vh[2], vh[3]);
                MMA16816(O[nd * 2 + 1], aPh[kc], vl[2], vl[3]);
            }
        }
        __syncthreads();
    }

    const float il0 = 1.0f / l0r, il1 = 1.0f / l1r;
    const int r0 = q0 + w * 16 + g;
    const int r1 = r0 + 8;
#pragma unroll
    for (int nt = 0; nt < 8; nt++) {
        const int col = h * 64 + nt * 8 + tg * 2;
        float2 w0 = make_float2(O[nt][0] * il0, O[nt][1] * il0);
        float2 w1 = make_float2(O[nt][2] * il1, O[nt][3] * il1);
        *(float2*)(out + ((size_t)b * 1024 + r0) * 1024 + col) = w0;
        *(float2*)(out + ((size_t)b * 1024 + r1) * 1024 + col) = w1;
    }
}

// ================= kernel_launch =================
extern "C" void kernel_launch(void* const* d_in, const int* in_sizes, int n_in,
                              void* d_out, int out_size)
{
    const float* q    = (const float*)d_in[0];
    const float* k    = (const float*)d_in[1];
    const float* v    = (const float*)d_in[2];
    const float* beta = (const float*)d_in[3];
    const unsigned char* srcm = (const unsigned char*)d_in[4];
    const unsigned char* tgtm = (const unsigned char*)d_in[5];
    const float* Wq = (const float*)d_in[6];
    const float* bq = (const float*)d_in[7];
    const float* Wk = (const float*)d_in[8];
    const float* bk = (const float*)d_in[9];
    const float* Wv = (const float*)d_in[10];
    const float* bv = (const float*)d_in[11];
    float* out = (float*)d_out;

    void *ah, *al, *bh, *bl;
    cudaGetSymbolAddress(&ah, g_ah);
    cudaGetSymbolAddress(&al, g_al);
    cudaGetSymbolAddress(&bh, g_bh);
    cudaGetSymbolAddress(&bl, g_bl);
    __nv_bfloat16* AH = (__nv_bfloat16*)ah;
    __nv_bfloat16* AL = (__nv_bfloat16*)al;
    __nv_bfloat16* BH = (__nv_bfloat16*)bh;
    __nv_bfloat16* BL = (__nv_bfloat16*)bl;

    cudaFuncSetAttribute(gemm_mma<0>, cudaFuncAttributeMaxDynamicSharedMemorySize, GSMEM_TOTAL);
    cudaFuncSetAttribute(gemm_mma<1>, cudaFuncAttributeMaxDynamicSharedMemorySize, GSMEM_TOTAL);
    cudaFuncSetAttribute(flash_tc, cudaFuncAttributeMaxDynamicSharedMemorySize, FSMEM);

    mask_convert<<<1, 1024>>>(srcm, Bb * TK, 0);
    mask_convert<<<1, 1024>>>(tgtm, Bb * TQ, 1);

    const int n4_act  = (MROWS * DIMX) / 4;   // 2M
    const int n4_w    = (DIMX * DIMX) / 4;    // 256K
    const int n4_beta = (NH * TQ * TK) / 4;   // 4M
    const size_t ACT = (size_t)8 * 1024 * 1024;   // elements per act segment
    const size_t WSEG = (size_t)1024 * 1024;

    // convert all activations + weights (packed segments)
    conv_split<<<(n4_act + 255) / 256, 256>>>((const float4*)q, AH,            AL,            n4_act);
    conv_split<<<(n4_act + 255) / 256, 256>>>((const float4*)k, AH + ACT,      AL + ACT,      n4_act);
    conv_split<<<(n4_act + 255) / 256, 256>>>((const float4*)v, AH + 2 * ACT,  AL + 2 * ACT,  n4_act);
    conv_split<<<(n4_w + 255) / 256, 256>>>((const float4*)Wq, BH,             BL,             n4_w);
    conv_split<<<(n4_w + 255) / 256, 256>>>((const float4*)Wk, BH + WSEG,      BL + WSEG,      n4_w);
    conv_split<<<(n4_w + 255) / 256, 256>>>((const float4*)Wv, BH + 2 * WSEG,  BL + 2 * WSEG,  n4_w);

    // fused QKV projection
    gemm_mma<0><<<dim3(24, 64), 256, GSMEM_TOTAL>>>(bq, bk, bv, nullptr);

    // tensor-core flash attention (writes out)
    flash_tc<<<dim3(TQ / 128, NH, Bb), 256, FSMEM>>>(out);

    // beta @ V accumulated into out (V consumed natural-layout via ldmatrix.trans)
    conv_split<<<(n4_beta + 255) / 256, 256>>>((const float4*)beta, AH, AL, n4_beta);
    gemm_mma<1><<<dim3(4, 8, 16), 256, GSMEM_TOTAL>>>(nullptr, nullptr, nullptr, out);
}

// round 6
// speedup vs baseline: 3.6442x; 1.0582x over previous
#include <cuda_runtime.h>
#include <cuda_bf16.h>
#include <math.h>
#include <stdint.h>

// Problem constants
#define Bb    8
#define TQ    1024
#define TK    1024
#define DIMX  1024
#define NH    16
#define HD    64
#define SCALE 0.03125f
#define NEGV  -1.0e9f
#define MROWS (Bb * TQ)  /* 8192 */
#define SC2L  (0.03125f * 1.44269504088896f)  /* scale * log2(e) */

// ================= PTX helpers (baseline ISA only) =================
__device__ __forceinline__ uint32_t smem_u32(const void* p) {
    uint32_t a;
    asm("{ .reg .u64 t; cvta.to.shared.u64 t, %1; cvt.u32.u64 %0, t; }"
        : "=r"(a) : "l"(p));
    return a;
}
#define CP_ASYNC16(dst_u32, src_ptr) \
    asm volatile("cp.async.cg.shared.global [%0], [%1], 16;" \
        :: "r"(dst_u32), "l"(src_ptr))
#define CP_COMMIT() asm volatile("cp.async.commit_group;" ::: "memory")
#define CP_WAIT(n)  asm volatile("cp.async.wait_group %0;" :: "n"(n) : "memory")

#define LDSM4(r, addr) \
    asm volatile("ldmatrix.sync.aligned.m8n8.x4.shared.b16 {%0,%1,%2,%3}, [%4];" \
        : "=r"((r)[0]), "=r"((r)[1]), "=r"((r)[2]), "=r"((r)[3]) : "r"(addr))
#define LDSM4T(r, addr) \
    asm volatile("ldmatrix.sync.aligned.m8n8.x4.trans.shared.b16 {%0,%1,%2,%3}, [%4];" \
        : "=r"((r)[0]), "=r"((r)[1]), "=r"((r)[2]), "=r"((r)[3]) : "r"(addr))

#define MMA16816(c, a, b0, b1) \
    asm volatile("mma.sync.aligned.m16n8k16.row.col.f32.bf16.bf16.f32 " \
        "{%0,%1,%2,%3}, {%4,%5,%6,%7}, {%8,%9}, {%0,%1,%2,%3};" \
        : "+f"((c)[0]), "+f"((c)[1]), "+f"((c)[2]), "+f"((c)[3]) \
        : "r"((a)[0]), "r"((a)[1]), "r"((a)[2]), "r"((a)[3]), "r"(b0), "r"(b1))

__device__ __forceinline__ uint32_t pbf2(float lo, float hi) {
    uint32_t d;
    asm("cvt.rn.bf16x2.f32 %0, %1, %2;" : "=r"(d) : "f"(hi), "f"(lo));
    return d;
}
__device__ __forceinline__ float ex2f(float x) {
    float y;
    asm("ex2.approx.ftz.f32 %0, %1;" : "=f"(y) : "f"(x));
    return y;
}

// ================= scratch (device globals, 16B aligned) =================
__device__ __align__(16) __nv_bfloat16 g_qph[(size_t)MROWS * DIMX];
__device__ __align__(16) __nv_bfloat16 g_qpl[(size_t)MROWS * DIMX];
__device__ __align__(16) __nv_bfloat16 g_kph[(size_t)MROWS * DIMX];
__device__ __align__(16) __nv_bfloat16 g_kpl[(size_t)MROWS * DIMX];
__device__ __align__(16) __nv_bfloat16 g_vph[(size_t)MROWS * DIMX];
__device__ __align__(16) __nv_bfloat16 g_vpl[(size_t)MROWS * DIMX];
__device__ __align__(16) __nv_bfloat16 g_ah[(size_t)24 * 1024 * 1024];  // acts q|k|v, or beta
__device__ __align__(16) __nv_bfloat16 g_al[(size_t)24 * 1024 * 1024];
__device__ __align__(16) __nv_bfloat16 g_bh[(size_t)3 * 1024 * 1024];   // weights q|k|v
__device__ __align__(16) __nv_bfloat16 g_bl[(size_t)3 * 1024 * 1024];
__device__ unsigned char g_src8[Bb * TK];
__device__ unsigned char g_tgt8[Bb * TQ];

// ================= mask canonicalization =================
__global__ void mask_convert(const unsigned char* __restrict__ raw, int n, int which)
{
    __shared__ int has3F, oddNZ;
    if (threadIdx.x == 0) { has3F = 0; oddNZ = 0; }
    __syncthreads();
    int lf = 0, lo = 0;
    for (int i = threadIdx.x; i < n; i += blockDim.x) {
        unsigned char c = raw[i];
        if (c == 0x3F) lf = 1;
        if ((i & 3) && c) lo = 1;
    }
    if (lf) atomicOr(&has3F, 1);
    if (lo) atomicOr(&oddNZ, 1);
    __syncthreads();
    unsigned char* out = which ? g_tgt8 : g_src8;
    int mode = has3F ? 2 : (oddNZ ? 0 : 1);
    for (int i = threadIdx.x; i < n; i += blockDim.x) {
        unsigned char v;
        if (mode == 2)      v = (((const float*)raw)[i] != 0.0f) ? 1 : 0;
        else if (mode == 1) v = (((const int*)raw)[i]   != 0)    ? 1 : 0;
        else                v = (raw[i] != 0) ? 1 : 0;
        out[i] = v;
    }
}

// ================= fp32 -> (bf16 hi, bf16 lo) split =================
__device__ __forceinline__ void split_store(const float4* __restrict__ x,
                                            __nv_bfloat16* __restrict__ hi,
                                            __nv_bfloat16* __restrict__ lo, size_t i)
{
    float4 f = x[i];
    __nv_bfloat16 h0 = __float2bfloat16_rn(f.x);
    __nv_bfloat16 h1 = __float2bfloat16_rn(f.y);
    __nv_bfloat16 h2 = __float2bfloat16_rn(f.z);
    __nv_bfloat16 h3 = __float2bfloat16_rn(f.w);
    __nv_bfloat16 l0 = __float2bfloat16_rn(f.x - __bfloat162float(h0));
    __nv_bfloat16 l1 = __float2bfloat16_rn(f.y - __bfloat162float(h1));
    __nv_bfloat16 l2 = __float2bfloat16_rn(f.z - __bfloat162float(h2));
    __nv_bfloat16 l3 = __float2bfloat16_rn(f.w - __bfloat162float(h3));
    __nv_bfloat162* Hp = (__nv_bfloat162*)(hi + 4 * i);
    __nv_bfloat162* Lp = (__nv_bfloat162*)(lo + 4 * i);
    Hp[0] = __halves2bfloat162(h0, h1);
    Hp[1] = __halves2bfloat162(h2, h3);
    Lp[0] = __halves2bfloat162(l0, l1);
    Lp[1] = __halves2bfloat162(l2, l3);
}

__global__ __launch_bounds__(256)
void conv_split(const float4* __restrict__ x, __nv_bfloat16* __restrict__ hi,
                __nv_bfloat16* __restrict__ lo, int n4)
{
    int i = blockIdx.x * 256 + threadIdx.x;
    if (i >= n4) return;
    split_store(x, hi, lo, i);
}

// Fused conversion of q,k,v (8192 blocks each) and Wq,Wk,Wv (1024 blocks each)
__global__ __launch_bounds__(256)
void conv_all(const float4* __restrict__ q, const float4* __restrict__ k,
              const float4* __restrict__ v, const float4* __restrict__ wq,
              const float4* __restrict__ wk, const float4* __restrict__ wv)
{
    const size_t ACT = (size_t)8 * 1024 * 1024;
    const size_t WSEG = (size_t)1024 * 1024;
    int bid = blockIdx.x;
    if (bid < 24576) {
        int seg = bid >> 13;           // /8192
        size_t i = ((size_t)(bid & 8191)) * 256 + threadIdx.x;
        const float4* src = (seg == 0) ? q : (seg == 1) ? k : v;
        split_store(src, g_ah + seg * ACT, g_al + seg * ACT, i);
    } else {
        bid -= 24576;
        int seg = bid >> 10;           // /1024
        size_t i = ((size_t)(bid & 1023)) * 256 + threadIdx.x;
        const float4* src = (seg == 0) ? wq : (seg == 1) ? wk : wv;
        split_store(src, g_bh + seg * WSEG, g_bl + seg * WSEG, i);
    }
}

// ================= mma.sync split-bf16 GEMM =================
// MODE 0 (fused QKV): seg = bx>>3 picks {A,W,bias,out}; Y = A @ W^T + bias -> bf16 hi/lo
// MODE 1 (beta@V):    out[b, bm+q, h*64+d] += beta_h @ V (V natural [k][d] via ldmatrix.trans)
#define NKCH 16
#define STG_B 65536
#define GSMEM_TOTAL (2 * STG_B)

extern __shared__ char smem_raw[];

template <int MODE>
__global__ __launch_bounds__(256)
void gemm_mma(const float* __restrict__ bias0, const float* __restrict__ bias1,
              const float* __restrict__ bias2, float* __restrict__ Yf)
{
    const uint32_t sb = smem_u32(smem_raw);
    const int tid  = threadIdx.x;
    const int lane = tid & 31;
    const int wid  = tid >> 5;
    const int wm = (wid >> 2) * 64;
    const int wn = (wid & 3) * 32;

    int bm, bn = 0, h = 0, b0 = 0, seg = 0;
    size_t arow0;
    const __nv_bfloat16 *Ahg, *Alg, *Bhg = nullptr, *Blg = nullptr;
    const float* bias = nullptr;
    __nv_bfloat16 *Yh = nullptr, *Yl = nullptr;
    if (MODE == 0) {
        seg = blockIdx.x >> 3;
        bn = (blockIdx.x & 7) * 128;
        bm = blockIdx.y * 128;
        arow0 = (size_t)bm;
        Ahg = g_ah + (size_t)seg * 8 * 1024 * 1024;
        Alg = g_al + (size_t)seg * 8 * 1024 * 1024;
        Bhg = g_bh + (size_t)seg * 1024 * 1024;
        Blg = g_bl + (size_t)seg * 1024 * 1024;
        bias = (seg == 0) ? bias0 : (seg == 1) ? bias1 : bias2;
        Yh = (seg == 0) ? g_qph : (seg == 1) ? g_kph : g_vph;
        Yl = (seg == 0) ? g_qpl : (seg == 1) ? g_kpl : g_vpl;
    } else {
        b0 = blockIdx.x * 2; bm = blockIdx.y * 128; h = blockIdx.z;
        arow0 = (size_t)h * 1024 + bm;
        Ahg = g_ah; Alg = g_al;
    }

    float C[4][4][4];
#pragma unroll
    for (int i = 0; i < 4; i++)
#pragma unroll
        for (int j = 0; j < 4; j++)
#pragma unroll
            for (int r = 0; r < 4; r++) C[i][j][r] = 0.0f;

    auto load_stage = [&](int s, int kc) {
        const uint32_t st = sb + s * STG_B;
        const int koff = kc * 64;
#pragma unroll
        for (int i = 0; i < 4; i++) {
            int idx = tid + i * 256;
            int row = idx >> 3, c = idx & 7;
            uint32_t off = row * 128 + c * 16;
            uint32_t sw = off ^ ((off >> 3) & 0x70);
            size_t gA = (arow0 + row) * 1024 + koff + c * 8;
            CP_ASYNC16(st + sw,          Ahg + gA);
            CP_ASYNC16(st + 16384 + sw,  Alg + gA);
        }
        if (MODE == 0) {
#pragma unroll
            for (int i = 0; i < 4; i++) {
                int idx = tid + i * 256;
                int row = idx >> 3, c = idx & 7;
                uint32_t off = row * 128 + c * 16;
                uint32_t sw = off ^ ((off >> 3) & 0x70);
                size_t gB = (size_t)(bn + row) * 1024 + koff + c * 8;
                CP_ASYNC16(st + 32768 + sw,  Bhg + gB);
                CP_ASYNC16(st + 49152 + sw,  Blg + gB);
            }
        } else {
#pragma unroll
            for (int i = 0; i < 4; i++) {
                int idx = tid + i * 256;
                int half = idx >> 9, row = (idx >> 3) & 63, c = idx & 7;
                uint32_t off = row * 128 + c * 16;
                uint32_t sw = off ^ ((off >> 3) & 0x70);
                size_t gV = ((size_t)(b0 + half) * 1024 + koff + row) * 1024 + h * 64 + c * 8;
                CP_ASYNC16(st + 32768 + half * 8192 + sw, g_vph + gV);
                CP_ASYNC16(st + 49152 + half * 8192 + sw, g_vpl + gV);
            }
        }
        CP_COMMIT();
    };

    const int q  = lane >> 3;
    const int lr = lane & 7;
    const int am_row = wm + (q & 1) * 8 + lr;
    const int a_kq   = (q >> 1) * 16;
    const int bn_row = wn + (q >> 1) * 8 + lr;
    const int b_kq   = (q & 1) * 16;

    load_stage(0, 0);

    for (int kc = 0; kc < NKCH; kc++) {
        if (kc + 1 < NKCH) { load_stage((kc + 1) & 1, kc + 1); CP_WAIT(1); }
        else               { CP_WAIT(0); }
        __syncthreads();

        const uint32_t st = sb + (kc & 1) * STG_B;
#pragma unroll
        for (int ks = 0; ks < 4; ks++) {
            uint32_t aH[4][4], aL[4][4], bH[2][4], bL[2][4];
#pragma unroll
            for (int i = 0; i < 4; i++) {
                uint32_t off = (uint32_t)(am_row + i * 16) * 128 + a_kq + ks * 32;
                uint32_t sw = off ^ ((off >> 3) & 0x70);
                LDSM4(aH[i], st + sw);
                LDSM4(aL[i], st + 16384 + sw);
            }
#pragma unroll
            for (int j2 = 0; j2 < 2; j2++) {
                if (MODE == 0) {
                    uint32_t off = (uint32_t)(bn_row + j2 * 16) * 128 + b_kq + ks * 32;
                    uint32_t sw = off ^ ((off >> 3) & 0x70);
                    LDSM4(bH[j2], st + 32768 + sw);
                    LDSM4(bL[j2], st + 49152 + sw);
                } else {
                    const int n16 = wn + j2 * 16;
                    const int half = n16 >> 6, d0 = n16 & 63;
                    uint32_t off = (uint32_t)(ks * 16 + (q & 1) * 8 + lr) * 128 +
                                   (d0 + (q >> 1) * 8) * 2;
                    uint32_t sw = off ^ ((off >> 3) & 0x70);
                    LDSM4T(bH[j2], st + 32768 + half * 8192 + sw);
                    LDSM4T(bL[j2], st + 49152 + half * 8192 + sw);
                }
            }
#pragma unroll
            for (int i = 0; i < 4; i++)
#pragma unroll
                for (int j = 0; j < 4; j++) {
                    const int jj = j >> 1, jo = (j & 1) * 2;
                    MMA16816(C[i][j], aH[i], bH[jj][jo], bH[jj][jo + 1]);
                    MMA16816(C[i][j], aH[i], bL[jj][jo], bL[jj][jo + 1]);
                    MMA16816(C[i][j], aL[i], bH[jj][jo], bH[jj][jo + 1]);
                }
        }
        __syncthreads();
    }

    const int g  = lane >> 2;
    const int tg = lane & 3;
#pragma unroll
    for (int i = 0; i < 4; i++) {
#pragma unroll
        for (int j = 0; j < 4; j++) {
            const int ncol = wn + j * 8 + tg * 2;
            const int r0 = bm + wm + i * 16 + g;
            const int r1 = r0 + 8;
            if (MODE == 0) {
                const int col = bn + ncol;
                float b0v = bias[col], b1v = bias[col + 1];
                float y00 = C[i][j][0] + b0v, y01 = C[i][j][1] + b1v;
                float y10 = C[i][j][2] + b0v, y11 = C[i][j][3] + b1v;
                float l00 = y00 - __bfloat162float(__float2bfloat16_rn(y00));
                float l01 = y01 - __bfloat162float(__float2bfloat16_rn(y01));
                float l10 = y10 - __bfloat162float(__float2bfloat16_rn(y10));
                float l11 = y11 - __bfloat162float(__float2bfloat16_rn(y11));
                *(uint32_t*)(Yh + (size_t)r0 * 1024 + col) = pbf2(y00, y01);
                *(uint32_t*)(Yh + (size_t)r1 * 1024 + col) = pbf2(y10, y11);
                *(uint32_t*)(Yl + (size_t)r0 * 1024 + col) = pbf2(l00, l01);
                *(uint32_t*)(Yl + (size_t)r1 * 1024 + col) = pbf2(l10, l11);
            } else {
                const int n = blockIdx.x * 128 + ncol;
                const int bb = n >> 6, dd = n & 63;
                float* p0 = Yf + ((size_t)bb * 1024 + r0) * 1024 + h * 64 + dd;
                float* p1 = Yf + ((size_t)bb * 1024 + r1) * 1024 + h * 64 + dd;
                float2 o0 = *(float2*)p0, o1 = *(float2*)p1;
                o0.x += C[i][j][0]; o0.y += C[i][j][1];
                o1.x += C[i][j][2]; o1.y += C[i][j][3];
                *(float2*)p0 = o0;
                *(float2*)p1 = o1;
            }
        }
    }
}

// ================= tensor-core flash attention (exp2 domain) =================
// S: 2-pass (qh*kh + qh*kl).  P*V: 2-pass (ph*vh + ph*vl).
#define FQH 0
#define FST0 16384
#define FKH 0
#define FKL 8192
#define FVH 16384
#define FVL 24576
#define FSRC 32768
#define FSTG 32896
#define FSMEM (16384 + 2 * FSTG)

__global__ __launch_bounds__(256)
void flash_tc(float* __restrict__ out)
{
    char* sm = smem_raw;
    const uint32_t sb = smem_u32(sm);
    const int tid  = threadIdx.x;
    const int lane = tid & 31;
    const int w    = tid >> 5;
    const int q0 = blockIdx.x * 128;
    const int h  = blockIdx.y;
    const int b  = blockIdx.z;
    const int g  = lane >> 2;
    const int tg = lane & 3;
    const int qq = lane >> 3;
    const int lr = lane & 7;

    {
#pragma unroll
        for (int i = 0; i < 4; i++) {
            int idx = tid + i * 256;
            int row = idx >> 3, c = idx & 7;
            uint32_t off = row * 128 + c * 16;
            uint32_t sw = off ^ ((off >> 3) & 0x70);
            size_t gq = ((size_t)b * 1024 + q0 + row) * 1024 + h * 64 + c * 8;
            CP_ASYNC16(sb + FQH + sw, g_qph + gq);
        }
        CP_COMMIT();
    }

    auto load_stage = [&](int s, int kt) {
        const uint32_t st = sb + FST0 + s * FSTG;
        const int k0 = kt * 64;
#pragma unroll
        for (int i = 0; i < 2; i++) {
            int idx = tid + i * 256;
            int row = idx >> 3, c = idx & 7;
            uint32_t off = row * 128 + c * 16;
            uint32_t sw = off ^ ((off >> 3) & 0x70);
            size_t gk = ((size_t)b * 1024 + k0 + row) * 1024 + h * 64 + c * 8;
            CP_ASYNC16(st + FKH + sw, g_kph + gk);
            CP_ASYNC16(st + FKL + sw, g_kpl + gk);
            CP_ASYNC16(st + FVH + sw, g_vph + gk);
            CP_ASYNC16(st + FVL + sw, g_vpl + gk);
        }
        if (tid < 4)
            CP_ASYNC16(st + FSRC + tid * 16, g_src8 + b * 1024 + k0 + tid * 16);
        CP_COMMIT();
    };

    load_stage(0, 0);

    const unsigned char t0m = g_tgt8[b * 1024 + q0 + w * 16 + g];
    const unsigned char t1m = g_tgt8[b * 1024 + q0 + w * 16 + 8 + g];

    float m0r = -3.0e38f, m1r = -3.0e38f, l0r = 0.0f, l1r = 0.0f;
    float O[8][4];
#pragma unroll
    for (int i = 0; i < 8; i++)
#pragma unroll
        for (int r = 0; r < 4; r++) O[i][r] = 0.0f;

    uint32_t aQh[4][4];

    for (int kt = 0; kt < 16; kt++) {
        if (kt + 1 < 16) { load_stage((kt + 1) & 1, kt + 1); CP_WAIT(1); }
        else             { CP_WAIT(0); }
        __syncthreads();

        if (kt == 0) {
#pragma unroll
            for (int kc = 0; kc < 4; kc++) {
                uint32_t off = (uint32_t)(w * 16 + (qq & 1) * 8 + lr) * 128 + (qq >> 1) * 16 + kc * 32;
                uint32_t sw = off ^ ((off >> 3) & 0x70);
                LDSM4(aQh[kc], sb + FQH + sw);
            }
        }

        const uint32_t st = sb + FST0 + (kt & 1) * FSTG;
        char* stp = sm + FST0 + (kt & 1) * FSTG;

        // ---- S = Qh @ (Kh + Kl)^T ----
        float C[8][4];
#pragma unroll
        for (int i = 0; i < 8; i++)
#pragma unroll
            for (int r = 0; r < 4; r++) C[i][r] = 0.0f;
#pragma unroll
        for (int ks = 0; ks < 4; ks++) {
#pragma unroll
            for (int j2 = 0; j2 < 4; j2++) {
                uint32_t bh[4], bl[4];
                uint32_t off = (uint32_t)(j2 * 16 + (qq >> 1) * 8 + lr) * 128 + (qq & 1) * 16 + ks * 32;
                uint32_t sw = off ^ ((off >> 3) & 0x70);
                LDSM4(bh, st + FKH + sw);
                LDSM4(bl, st + FKL + sw);
                MMA16816(C[j2 * 2],     aQh[ks], bh[0], bh[1]);
                MMA16816(C[j2 * 2],     aQh[ks], bl[0], bl[1]);
                MMA16816(C[j2 * 2 + 1], aQh[ks], bh[2], bh[3]);
                MMA16816(C[j2 * 2 + 1], aQh[ks], bl[2], bl[3]);
            }
        }

        // ---- mask + online softmax (log2 domain) ----
        float mx0 = -3.0e38f, mx1 = -3.0e38f;
#pragma unroll
        for (int nt = 0; nt < 8; nt++) {
            unsigned char s0 = *(unsigned char*)(stp + FSRC + nt * 8 + tg * 2);
            unsigned char s1 = *(unsigned char*)(stp + FSRC + nt * 8 + tg * 2 + 1);
            C[nt][0] = (t0m && s0) ? C[nt][0] * SC2L : NEGV;
            C[nt][1] = (t0m && s1) ? C[nt][1] * SC2L : NEGV;
            C[nt][2] = (t1m && s0) ? C[nt][2] * SC2L : NEGV;
            C[nt][3] = (t1m && s1) ? C[nt][3] * SC2L : NEGV;
            mx0 = fmaxf(mx0, fmaxf(C[nt][0], C[nt][1]));
            mx1 = fmaxf(mx1, fmaxf(C[nt][2], C[nt][3]));
        }
        mx0 = fmaxf(mx0, __shfl_xor_sync(0xFFFFFFFF, mx0, 1));
        mx0 = fmaxf(mx0, __shfl_xor_sync(0xFFFFFFFF, mx0, 2));
        mx1 = fmaxf(mx1, __shfl_xor_sync(0xFFFFFFFF, mx1, 1));
        mx1 = fmaxf(mx1, __shfl_xor_sync(0xFFFFFFFF, mx1, 2));

        float mn0 = fmaxf(m0r, mx0), mn1 = fmaxf(m1r, mx1);
        float f0 = ex2f(m0r - mn0), f1 = ex2f(m1r - mn1);
        m0r = mn0; m1r = mn1;

        float s0 = 0.0f, s1 = 0.0f;
#pragma unroll
        for (int nt = 0; nt < 8; nt++) {
            C[nt][0] = ex2f(C[nt][0] - mn0);
            C[nt][1] = ex2f(C[nt][1] - mn0);
            C[nt][2] = ex2f(C[nt][2] - mn1);
            C[nt][3] = ex2f(C[nt][3] - mn1);
            s0 += C[nt][0] + C[nt][1];
            s1 += C[nt][2] + C[nt][3];
        }
        s0 += __shfl_xor_sync(0xFFFFFFFF, s0, 1);
        s0 += __shfl_xor_sync(0xFFFFFFFF, s0, 2);
        s1 += __shfl_xor_sync(0xFFFFFFFF, s1, 1);
        s1 += __shfl_xor_sync(0xFFFFFFFF, s1, 2);
        l0r = l0r * f0 + s0;
        l1r = l1r * f1 + s1;

#pragma unroll
        for (int nt = 0; nt < 8; nt++) {
            O[nt][0] *= f0; O[nt][1] *= f0;
            O[nt][2] *= f1; O[nt][3] *= f1;
        }

        // ---- pack P (hi only) into A-frags ----
        uint32_t aPh[4][4];
#pragma unroll
        for (int kc = 0; kc < 4; kc++) {
            const int n0 = kc * 2, n1 = kc * 2 + 1;
            aPh[kc][0] = pbf2(C[n0][0], C[n0][1]);
            aPh[kc][1] = pbf2(C[n0][2], C[n0][3]);
            aPh[kc][2] = pbf2(C[n1][0], C[n1][1]);
            aPh[kc][3] = pbf2(C[n1][2], C[n1][3]);
        }

        // ---- O += Ph @ (Vh + Vl) ----
#pragma unroll
        for (int kc = 0; kc < 4; kc++) {
#pragma unroll
            for (int nd = 0; nd < 4; nd++) {
                uint32_t vh[4], vl[4];
                uint32_t off = (uint32_t)(kc * 16 + (qq & 1) * 8 + lr) * 128 +
                               (nd * 16 + (qq >> 1) * 8) * 2;
                uint32_t sw = off ^ ((off >> 3) & 0x70);
                LDSM4T(vh, st + FVH + sw);
                LDSM4T(vl, st + FVL + sw);
                MMA16816(O[nd * 2],     aPh[kc], vh[0], vh[1]);
                MMA16816(O[nd * 2],     aPh[kc], vl[0], vl[1]);
                MMA16816(O[nd * 2 + 1], aPh[kc], vh[2], vh[3]);
                MMA16816(O[nd * 2 + 1], aPh[kc], vl[2], vl[3]);
            }
        }
        __syncthreads();
    }

    const float il0 = 1.0f / l0r, il1 = 1.0f / l1r;
    const int r0 = q0 + w * 16 + g;
    const int r1 = r0 + 8;
#pragma unroll
    for (int nt = 0; nt < 8; nt++) {
        const int col = h * 64 + nt * 8 + tg * 2;
        float2 w0 = make_float2(O[nt][0] * il0, O[nt][1] * il0);
        float2 w1 = make_float2(O[nt][2] * il1, O[nt][3] * il1);
        *(float2*)(out + ((size_t)b * 1024 + r0) * 1024 + col) = w0;
        *(float2*)(out + ((size_t)b * 1024 + r1) * 1024 + col) = w1;
    }
}

// ================= kernel_launch =================
extern "C" void kernel_launch(void* const* d_in, const int* in_sizes, int n_in,
                              void* d_out, int out_size)
{
    const float* q    = (const float*)d_in[0];
    const float* k    = (const float*)d_in[1];
    const float* v    = (const float*)d_in[2];
    const float* beta = (const float*)d_in[3];
    const unsigned char* srcm = (const unsigned char*)d_in[4];
    const unsigned char* tgtm = (const unsigned char*)d_in[5];
    const float* Wq = (const float*)d_in[6];
    const float* bq = (const float*)d_in[7];
    const float* Wk = (const float*)d_in[8];
    const float* bk = (const float*)d_in[9];
    const float* Wv = (const float*)d_in[10];
    const float* bv = (const float*)d_in[11];
    float* out = (float*)d_out;

    void *ah, *al;
    cudaGetSymbolAddress(&ah, g_ah);
    cudaGetSymbolAddress(&al, g_al);
    __nv_bfloat16* AH = (__nv_bfloat16*)ah;
    __nv_bfloat16* AL = (__nv_bfloat16*)al;

    cudaFuncSetAttribute(gemm_mma<0>, cudaFuncAttributeMaxDynamicSharedMemorySize, GSMEM_TOTAL);
    cudaFuncSetAttribute(gemm_mma<1>, cudaFuncAttributeMaxDynamicSharedMemorySize, GSMEM_TOTAL);
    cudaFuncSetAttribute(flash_tc, cudaFuncAttributeMaxDynamicSharedMemorySize, FSMEM);

    mask_convert<<<1, 1024>>>(srcm, Bb * TK, 0);
    mask_convert<<<1, 1024>>>(tgtm, Bb * TQ, 1);

    // fused conversion of all activations + weights
    conv_all<<<27648, 256>>>((const float4*)q, (const float4*)k, (const float4*)v,
                             (const float4*)Wq, (const float4*)Wk, (const float4*)Wv);

    // fused QKV projection
    gemm_mma<0><<<dim3(24, 64), 256, GSMEM_TOTAL>>>(bq, bk, bv, nullptr);

    // tensor-core flash attention (writes out)
    flash_tc<<<dim3(TQ / 128, NH, Bb), 256, FSMEM>>>(out);

    // beta @ V accumulated into out
    const int n4_beta = (NH * TQ * TK) / 4;
    conv_split<<<(n4_beta + 255) / 256, 256>>>((const float4*)beta, AH, AL, n4_beta);
    gemm_mma<1><<<dim3(4, 8, 16), 256, GSMEM_TOTAL>>>(nullptr, nullptr, nullptr, out);
}

// round 7
// speedup vs baseline: 3.8858x; 1.0663x over previous
#include <cuda_runtime.h>
#include <cuda_bf16.h>
#include <math.h>
#include <stdint.h>

// Problem constants
#define Bb    8
#define TQ    1024
#define TK    1024
#define DIMX  1024
#define NH    16
#define HD    64
#define SCALE 0.03125f
#define NEGV  -1.0e9f
#define MROWS (Bb * TQ)  /* 8192 */
#define SC2L  (0.03125f * 1.44269504088896f)  /* scale * log2(e) */

// ================= PTX helpers (baseline ISA only) =================
__device__ __forceinline__ uint32_t smem_u32(const void* p) {
    uint32_t a;
    asm("{ .reg .u64 t; cvta.to.shared.u64 t, %1; cvt.u32.u64 %0, t; }"
        : "=r"(a) : "l"(p));
    return a;
}
#define CP_ASYNC16(dst_u32, src_ptr) \
    asm volatile("cp.async.cg.shared.global [%0], [%1], 16;" \
        :: "r"(dst_u32), "l"(src_ptr))
#define CP_COMMIT() asm volatile("cp.async.commit_group;" ::: "memory")
#define CP_WAIT(n)  asm volatile("cp.async.wait_group %0;" :: "n"(n) : "memory")

#define LDSM4(r, addr) \
    asm volatile("ldmatrix.sync.aligned.m8n8.x4.shared.b16 {%0,%1,%2,%3}, [%4];" \
        : "=r"((r)[0]), "=r"((r)[1]), "=r"((r)[2]), "=r"((r)[3]) : "r"(addr))
#define LDSM4T(r, addr) \
    asm volatile("ldmatrix.sync.aligned.m8n8.x4.trans.shared.b16 {%0,%1,%2,%3}, [%4];" \
        : "=r"((r)[0]), "=r"((r)[1]), "=r"((r)[2]), "=r"((r)[3]) : "r"(addr))

#define MMA16816(c, a, b0, b1) \
    asm volatile("mma.sync.aligned.m16n8k16.row.col.f32.bf16.bf16.f32 " \
        "{%0,%1,%2,%3}, {%4,%5,%6,%7}, {%8,%9}, {%0,%1,%2,%3};" \
        : "+f"((c)[0]), "+f"((c)[1]), "+f"((c)[2]), "+f"((c)[3]) \
        : "r"((a)[0]), "r"((a)[1]), "r"((a)[2]), "r"((a)[3]), "r"(b0), "r"(b1))

__device__ __forceinline__ uint32_t pbf2(float lo, float hi) {
    uint32_t d;
    asm("cvt.rn.bf16x2.f32 %0, %1, %2;" : "=r"(d) : "f"(hi), "f"(lo));
    return d;
}
__device__ __forceinline__ float ex2f(float x) {
    float y;
    asm("ex2.approx.ftz.f32 %0, %1;" : "=f"(y) : "f"(x));
    return y;
}

// ================= scratch (device globals, 16B aligned) =================
__device__ __align__(16) __nv_bfloat16 g_qph[(size_t)MROWS * DIMX];
__device__ __align__(16) __nv_bfloat16 g_kph[(size_t)MROWS * DIMX];
__device__ __align__(16) __nv_bfloat16 g_vph[(size_t)MROWS * DIMX];
__device__ __align__(16) __nv_bfloat16 g_vpl[(size_t)MROWS * DIMX];
__device__ __align__(16) __nv_bfloat16 g_ah[(size_t)24 * 1024 * 1024];  // acts q|k|v, or beta
__device__ __align__(16) __nv_bfloat16 g_al[(size_t)24 * 1024 * 1024];
__device__ __align__(16) __nv_bfloat16 g_bh[(size_t)3 * 1024 * 1024];   // weights q|k|v
__device__ __align__(16) __nv_bfloat16 g_bl[(size_t)3 * 1024 * 1024];
__device__ unsigned char g_src8[Bb * TK];
__device__ unsigned char g_tgt8[Bb * TQ];

// ================= mask canonicalization =================
__global__ void mask_convert(const unsigned char* __restrict__ raw, int n, int which)
{
    __shared__ int has3F, oddNZ;
    if (threadIdx.x == 0) { has3F = 0; oddNZ = 0; }
    __syncthreads();
    int lf = 0, lo = 0;
    for (int i = threadIdx.x; i < n; i += blockDim.x) {
        unsigned char c = raw[i];
        if (c == 0x3F) lf = 1;
        if ((i & 3) && c) lo = 1;
    }
    if (lf) atomicOr(&has3F, 1);
    if (lo) atomicOr(&oddNZ, 1);
    __syncthreads();
    unsigned char* out = which ? g_tgt8 : g_src8;
    int mode = has3F ? 2 : (oddNZ ? 0 : 1);
    for (int i = threadIdx.x; i < n; i += blockDim.x) {
        unsigned char v;
        if (mode == 2)      v = (((const float*)raw)[i] != 0.0f) ? 1 : 0;
        else if (mode == 1) v = (((const int*)raw)[i]   != 0)    ? 1 : 0;
        else                v = (raw[i] != 0) ? 1 : 0;
        out[i] = v;
    }
}

// ================= fp32 -> (bf16 hi, bf16 lo) split =================
__device__ __forceinline__ void split_store(const float4* __restrict__ x,
                                            __nv_bfloat16* __restrict__ hi,
                                            __nv_bfloat16* __restrict__ lo, size_t i)
{
    float4 f = x[i];
    __nv_bfloat16 h0 = __float2bfloat16_rn(f.x);
    __nv_bfloat16 h1 = __float2bfloat16_rn(f.y);
    __nv_bfloat16 h2 = __float2bfloat16_rn(f.z);
    __nv_bfloat16 h3 = __float2bfloat16_rn(f.w);
    __nv_bfloat16 l0 = __float2bfloat16_rn(f.x - __bfloat162float(h0));
    __nv_bfloat16 l1 = __float2bfloat16_rn(f.y - __bfloat162float(h1));
    __nv_bfloat16 l2 = __float2bfloat16_rn(f.z - __bfloat162float(h2));
    __nv_bfloat16 l3 = __float2bfloat16_rn(f.w - __bfloat162float(h3));
    __nv_bfloat162* Hp = (__nv_bfloat162*)(hi + 4 * i);
    __nv_bfloat162* Lp = (__nv_bfloat162*)(lo + 4 * i);
    Hp[0] = __halves2bfloat162(h0, h1);
    Hp[1] = __halves2bfloat162(h2, h3);
    Lp[0] = __halves2bfloat162(l0, l1);
    Lp[1] = __halves2bfloat162(l2, l3);
}

__global__ __launch_bounds__(256)
void conv_split(const float4* __restrict__ x, __nv_bfloat16* __restrict__ hi,
                __nv_bfloat16* __restrict__ lo, int n4)
{
    int i = blockIdx.x * 256 + threadIdx.x;
    if (i >= n4) return;
    split_store(x, hi, lo, i);
}

// Fused conversion of q,k,v (8192 blocks each) and Wq,Wk,Wv (1024 blocks each)
__global__ __launch_bounds__(256)
void conv_all(const float4* __restrict__ q, const float4* __restrict__ k,
              const float4* __restrict__ v, const float4* __restrict__ wq,
              const float4* __restrict__ wk, const float4* __restrict__ wv)
{
    const size_t ACT = (size_t)8 * 1024 * 1024;
    const size_t WSEG = (size_t)1024 * 1024;
    int bid = blockIdx.x;
    if (bid < 24576) {
        int seg = bid >> 13;
        size_t i = ((size_t)(bid & 8191)) * 256 + threadIdx.x;
        const float4* src = (seg == 0) ? q : (seg == 1) ? k : v;
        split_store(src, g_ah + seg * ACT, g_al + seg * ACT, i);
    } else {
        bid -= 24576;
        int seg = bid >> 10;
        size_t i = ((size_t)(bid & 1023)) * 256 + threadIdx.x;
        const float4* src = (seg == 0) ? wq : (seg == 1) ? wk : wv;
        split_store(src, g_bh + seg * WSEG, g_bl + seg * WSEG, i);
    }
}

// ================= mma.sync split-bf16 GEMM (3-stage pipeline) =================
// MODE 0 (fused QKV): seg 0/1 (Q,K) 2-pass, hi-only output; seg 2 (V) 3-pass, hi/lo.
// MODE 1 (beta@V):    out += beta_h @ V, 3-pass.
#define NKCH 16
#define STG_B 65536
#define GSMEM_TOTAL (3 * STG_B)

extern __shared__ char smem_raw[];

template <int MODE>
__global__ __launch_bounds__(256)
void gemm_mma(const float* __restrict__ bias0, const float* __restrict__ bias1,
              const float* __restrict__ bias2, float* __restrict__ Yf)
{
    const uint32_t sb = smem_u32(smem_raw);
    const int tid  = threadIdx.x;
    const int lane = tid & 31;
    const int wid  = tid >> 5;
    const int wm = (wid >> 2) * 64;
    const int wn = (wid & 3) * 32;

    int bm, bn = 0, h = 0, b0 = 0, seg = 0;
    size_t arow0;
    const __nv_bfloat16 *Ahg, *Alg, *Bhg = nullptr, *Blg = nullptr;
    const float* bias = nullptr;
    __nv_bfloat16 *Yh = nullptr, *Yl = nullptr;
    if (MODE == 0) {
        seg = blockIdx.x >> 3;
        bn = (blockIdx.x & 7) * 128;
        bm = blockIdx.y * 128;
        arow0 = (size_t)bm;
        Ahg = g_ah + (size_t)seg * 8 * 1024 * 1024;
        Alg = g_al + (size_t)seg * 8 * 1024 * 1024;
        Bhg = g_bh + (size_t)seg * 1024 * 1024;
        Blg = g_bl + (size_t)seg * 1024 * 1024;
        bias = (seg == 0) ? bias0 : (seg == 1) ? bias1 : bias2;
        Yh = (seg == 0) ? g_qph : (seg == 1) ? g_kph : g_vph;
        Yl = (seg == 2) ? g_vpl : nullptr;
    } else {
        b0 = blockIdx.x * 2; bm = blockIdx.y * 128; h = blockIdx.z;
        arow0 = (size_t)h * 1024 + bm;
        Ahg = g_ah; Alg = g_al;
    }
    const bool full = (MODE == 1) || (seg == 2);   // 3-pass?

    float C[4][4][4];
#pragma unroll
    for (int i = 0; i < 4; i++)
#pragma unroll
        for (int j = 0; j < 4; j++)
#pragma unroll
            for (int r = 0; r < 4; r++) C[i][j][r] = 0.0f;

    auto load_stage = [&](int s, int kc) {
        const uint32_t st = sb + s * STG_B;
        const int koff = kc * 64;
#pragma unroll
        for (int i = 0; i < 4; i++) {
            int idx = tid + i * 256;
            int row = idx >> 3, c = idx & 7;
            uint32_t off = row * 128 + c * 16;
            uint32_t sw = off ^ ((off >> 3) & 0x70);
            size_t gA = (arow0 + row) * 1024 + koff + c * 8;
            CP_ASYNC16(st + sw, Ahg + gA);
            if (full) CP_ASYNC16(st + 16384 + sw, Alg + gA);
        }
        if (MODE == 0) {
#pragma unroll
            for (int i = 0; i < 4; i++) {
                int idx = tid + i * 256;
                int row = idx >> 3, c = idx & 7;
                uint32_t off = row * 128 + c * 16;
                uint32_t sw = off ^ ((off >> 3) & 0x70);
                size_t gB = (size_t)(bn + row) * 1024 + koff + c * 8;
                CP_ASYNC16(st + 32768 + sw,  Bhg + gB);
                CP_ASYNC16(st + 49152 + sw,  Blg + gB);
            }
        } else {
#pragma unroll
            for (int i = 0; i < 4; i++) {
                int idx = tid + i * 256;
                int half = idx >> 9, row = (idx >> 3) & 63, c = idx & 7;
                uint32_t off = row * 128 + c * 16;
                uint32_t sw = off ^ ((off >> 3) & 0x70);
                size_t gV = ((size_t)(b0 + half) * 1024 + koff + row) * 1024 + h * 64 + c * 8;
                CP_ASYNC16(st + 32768 + half * 8192 + sw, g_vph + gV);
                CP_ASYNC16(st + 49152 + half * 8192 + sw, g_vpl + gV);
            }
        }
        CP_COMMIT();
    };

    const int q  = lane >> 3;
    const int lr = lane & 7;
    const int am_row = wm + (q & 1) * 8 + lr;
    const int a_kq   = (q >> 1) * 16;
    const int bn_row = wn + (q >> 1) * 8 + lr;
    const int b_kq   = (q & 1) * 16;

    load_stage(0, 0);
    load_stage(1, 1);

    for (int kc = 0; kc < NKCH; kc++) {
        if (kc < NKCH - 1) CP_WAIT(1); else CP_WAIT(0);
        __syncthreads();
        if (kc + 2 < NKCH) load_stage((kc + 2) % 3, kc + 2);

        const uint32_t st = sb + (kc % 3) * STG_B;
#pragma unroll
        for (int ks = 0; ks < 4; ks++) {
            uint32_t aH[4][4], aL[4][4], bH[2][4], bL[2][4];
#pragma unroll
            for (int i = 0; i < 4; i++) {
                uint32_t off = (uint32_t)(am_row + i * 16) * 128 + a_kq + ks * 32;
                uint32_t sw = off ^ ((off >> 3) & 0x70);
                LDSM4(aH[i], st + sw);
                if (full) LDSM4(aL[i], st + 16384 + sw);
            }
#pragma unroll
            for (int j2 = 0; j2 < 2; j2++) {
                if (MODE == 0) {
                    uint32_t off = (uint32_t)(bn_row + j2 * 16) * 128 + b_kq + ks * 32;
                    uint32_t sw = off ^ ((off >> 3) & 0x70);
                    LDSM4(bH[j2], st + 32768 + sw);
                    LDSM4(bL[j2], st + 49152 + sw);
                } else {
                    const int n16 = wn + j2 * 16;
                    const int half = n16 >> 6, d0 = n16 & 63;
                    uint32_t off = (uint32_t)(ks * 16 + (q & 1) * 8 + lr) * 128 +
                                   (d0 + (q >> 1) * 8) * 2;
                    uint32_t sw = off ^ ((off >> 3) & 0x70);
                    LDSM4T(bH[j2], st + 32768 + half * 8192 + sw);
                    LDSM4T(bL[j2], st + 49152 + half * 8192 + sw);
                }
            }
#pragma unroll
            for (int i = 0; i < 4; i++)
#pragma unroll
                for (int j = 0; j < 4; j++) {
                    const int jj = j >> 1, jo = (j & 1) * 2;
                    MMA16816(C[i][j], aH[i], bH[jj][jo], bH[jj][jo + 1]);
                    MMA16816(C[i][j], aH[i], bL[jj][jo], bL[jj][jo + 1]);
                    if (full) MMA16816(C[i][j], aL[i], bH[jj][jo], bH[jj][jo + 1]);
                }
        }
    }

    const int g  = lane >> 2;
    const int tg = lane & 3;
#pragma unroll
    for (int i = 0; i < 4; i++) {
#pragma unroll
        for (int j = 0; j < 4; j++) {
            const int ncol = wn + j * 8 + tg * 2;
            const int r0 = bm + wm + i * 16 + g;
            const int r1 = r0 + 8;
            if (MODE == 0) {
                const int col = bn + ncol;
                float b0v = bias[col], b1v = bias[col + 1];
                float y00 = C[i][j][0] + b0v, y01 = C[i][j][1] + b1v;
                float y10 = C[i][j][2] + b0v, y11 = C[i][j][3] + b1v;
                *(uint32_t*)(Yh + (size_t)r0 * 1024 + col) = pbf2(y00, y01);
                *(uint32_t*)(Yh + (size_t)r1 * 1024 + col) = pbf2(y10, y11);
                if (full) {
                    float l00 = y00 - __bfloat162float(__float2bfloat16_rn(y00));
                    float l01 = y01 - __bfloat162float(__float2bfloat16_rn(y01));
                    float l10 = y10 - __bfloat162float(__float2bfloat16_rn(y10));
                    float l11 = y11 - __bfloat162float(__float2bfloat16_rn(y11));
                    *(uint32_t*)(Yl + (size_t)r0 * 1024 + col) = pbf2(l00, l01);
                    *(uint32_t*)(Yl + (size_t)r1 * 1024 + col) = pbf2(l10, l11);
                }
            } else {
                const int n = blockIdx.x * 128 + ncol;
                const int bb = n >> 6, dd = n & 63;
                float* p0 = Yf + ((size_t)bb * 1024 + r0) * 1024 + h * 64 + dd;
                float* p1 = Yf + ((size_t)bb * 1024 + r1) * 1024 + h * 64 + dd;
                float2 o0 = *(float2*)p0, o1 = *(float2*)p1;
                o0.x += C[i][j][0]; o0.y += C[i][j][1];
                o1.x += C[i][j][2]; o1.y += C[i][j][3];
                *(float2*)p0 = o0;
                *(float2*)p1 = o1;
            }
        }
    }
}

// ================= tensor-core flash attention (3-stage, exp2) =================
// S: 1-pass (qh*kh).  P*V: 2-pass (ph*vh + ph*vl).
#define FQH 0
#define FST0 16384
#define FKH 0
#define FVH 8192
#define FVL 16384
#define FSRC 24576
#define FSTG 24704
#define FSMEM (16384 + 3 * FSTG)

__global__ __launch_bounds__(256)
void flash_tc(float* __restrict__ out)
{
    char* sm = smem_raw;
    const uint32_t sb = smem_u32(sm);
    const int tid  = threadIdx.x;
    const int lane = tid & 31;
    const int w    = tid >> 5;
    const int q0 = blockIdx.x * 128;
    const int h  = blockIdx.y;
    const int b  = blockIdx.z;
    const int g  = lane >> 2;
    const int tg = lane & 3;
    const int qq = lane >> 3;
    const int lr = lane & 7;

    {
#pragma unroll
        for (int i = 0; i < 4; i++) {
            int idx = tid + i * 256;
            int row = idx >> 3, c = idx & 7;
            uint32_t off = row * 128 + c * 16;
            uint32_t sw = off ^ ((off >> 3) & 0x70);
            size_t gq = ((size_t)b * 1024 + q0 + row) * 1024 + h * 64 + c * 8;
            CP_ASYNC16(sb + FQH + sw, g_qph + gq);
        }
        CP_COMMIT();
    }

    auto load_stage = [&](int s, int kt) {
        const uint32_t st = sb + FST0 + s * FSTG;
        const int k0 = kt * 64;
#pragma unroll
        for (int i = 0; i < 2; i++) {
            int idx = tid + i * 256;
            int row = idx >> 3, c = idx & 7;
            uint32_t off = row * 128 + c * 16;
            uint32_t sw = off ^ ((off >> 3) & 0x70);
            size_t gk = ((size_t)b * 1024 + k0 + row) * 1024 + h * 64 + c * 8;
            CP_ASYNC16(st + FKH + sw, g_kph + gk);
            CP_ASYNC16(st + FVH + sw, g_vph + gk);
            CP_ASYNC16(st + FVL + sw, g_vpl + gk);
        }
        if (tid < 4)
            CP_ASYNC16(st + FSRC + tid * 16, g_src8 + b * 1024 + k0 + tid * 16);
        CP_COMMIT();
    };

    load_stage(0, 0);
    load_stage(1, 1);

    const unsigned char t0m = g_tgt8[b * 1024 + q0 + w * 16 + g];
    const unsigned char t1m = g_tgt8[b * 1024 + q0 + w * 16 + 8 + g];

    float m0r = -3.0e38f, m1r = -3.0e38f, l0r = 0.0f, l1r = 0.0f;
    float O[8][4];
#pragma unroll
    for (int i = 0; i < 8; i++)
#pragma unroll
        for (int r = 0; r < 4; r++) O[i][r] = 0.0f;

    uint32_t aQh[4][4];

    for (int kt = 0; kt < 16; kt++) {
        if (kt < 15) CP_WAIT(1); else CP_WAIT(0);
        __syncthreads();
        if (kt + 2 < 16) load_stage((kt + 2) % 3, kt + 2);

        if (kt == 0) {
#pragma unroll
            for (int kc = 0; kc < 4; kc++) {
                uint32_t off = (uint32_t)(w * 16 + (qq & 1) * 8 + lr) * 128 + (qq >> 1) * 16 + kc * 32;
                uint32_t sw = off ^ ((off >> 3) & 0x70);
                LDSM4(aQh[kc], sb + FQH + sw);
            }
        }

        const uint32_t st = sb + FST0 + (kt % 3) * FSTG;
        char* stp = sm + FST0 + (kt % 3) * FSTG;

        // ---- S = Qh @ Kh^T (1-pass) ----
        float C[8][4];
#pragma unroll
        for (int i = 0; i < 8; i++)
#pragma unroll
            for (int r = 0; r < 4; r++) C[i][r] = 0.0f;
#pragma unroll
        for (int ks = 0; ks < 4; ks++) {
#pragma unroll
            for (int j2 = 0; j2 < 4; j2++) {
                uint32_t bh[4];
                uint32_t off = (uint32_t)(j2 * 16 + (qq >> 1) * 8 + lr) * 128 + (qq & 1) * 16 + ks * 32;
                uint32_t sw = off ^ ((off >> 3) & 0x70);
                LDSM4(bh, st + FKH + sw);
                MMA16816(C[j2 * 2],     aQh[ks], bh[0], bh[1]);
                MMA16816(C[j2 * 2 + 1], aQh[ks], bh[2], bh[3]);
            }
        }

        // ---- mask + online softmax (log2 domain) ----
        float mx0 = -3.0e38f, mx1 = -3.0e38f;
#pragma unroll
        for (int nt = 0; nt < 8; nt++) {
            unsigned char s0 = *(unsigned char*)(stp + FSRC + nt * 8 + tg * 2);
            unsigned char s1 = *(unsigned char*)(stp + FSRC + nt * 8 + tg * 2 + 1);
            C[nt][0] = (t0m && s0) ? C[nt][0] * SC2L : NEGV;
            C[nt][1] = (t0m && s1) ? C[nt][1] * SC2L : NEGV;
            C[nt][2] = (t1m && s0) ? C[nt][2] * SC2L : NEGV;
            C[nt][3] = (t1m && s1) ? C[nt][3] * SC2L : NEGV;
            mx0 = fmaxf(mx0, fmaxf(C[nt][0], C[nt][1]));
            mx1 = fmaxf(mx1, fmaxf(C[nt][2], C[nt][3]));
        }
        mx0 = fmaxf(mx0, __shfl_xor_sync(0xFFFFFFFF, mx0, 1));
        mx0 = fmaxf(mx0, __shfl_xor_sync(0xFFFFFFFF, mx0, 2));
        mx1 = fmaxf(mx1, __shfl_xor_sync(0xFFFFFFFF, mx1, 1));
        mx1 = fmaxf(mx1, __shfl_xor_sync(0xFFFFFFFF, mx1, 2));

        float mn0 = fmaxf(m0r, mx0), mn1 = fmaxf(m1r, mx1);
        float f0 = ex2f(m0r - mn0), f1 = ex2f(m1r - mn1);
        m0r = mn0; m1r = mn1;

        float s0 = 0.0f, s1 = 0.0f;
#pragma unroll
        for (int nt = 0; nt < 8; nt++) {
            C[nt][0] = ex2f(C[nt][0] - mn0);
            C[nt][1] = ex2f(C[nt][1] - mn0);
            C[nt][2] = ex2f(C[nt][2] - mn1);
            C[nt][3] = ex2f(C[nt][3] - mn1);
            s0 += C[nt][0] + C[nt][1];
            s1 += C[nt][2] + C[nt][3];
        }
        s0 += __shfl_xor_sync(0xFFFFFFFF, s0, 1);
        s0 += __shfl_xor_sync(0xFFFFFFFF, s0, 2);
        s1 += __shfl_xor_sync(0xFFFFFFFF, s1, 1);
        s1 += __shfl_xor_sync(0xFFFFFFFF, s1, 2);
        l0r = l0r * f0 + s0;
        l1r = l1r * f1 + s1;

#pragma unroll
        for (int nt = 0; nt < 8; nt++) {
            O[nt][0] *= f0; O[nt][1] *= f0;
            O[nt][2] *= f1; O[nt][3] *= f1;
        }

        // ---- pack P (hi only) into A-frags ----
        uint32_t aPh[4][4];
#pragma unroll
        for (int kc = 0; kc < 4; kc++) {
            const int n0 = kc * 2, n1 = kc * 2 + 1;
            aPh[kc][0] = pbf2(C[n0][0], C[n0][1]);
            aPh[kc][1] = pbf2(C[n0][2], C[n0][3]);
            aPh[kc][2] = pbf2(C[n1][0], C[n1][1]);
            aPh[kc][3] = pbf2(C[n1][2], C[n1][3]);
        }

        // ---- O += Ph @ (Vh + Vl) ----
#pragma unroll
        for (int kc = 0; kc < 4; kc++) {
#pragma unroll
            for (int nd = 0; nd < 4; nd++) {
                uint32_t vh[4], vl[4];
                uint32_t off = (uint32_t)(kc * 16 + (qq & 1) * 8 + lr) * 128 +
                               (nd * 16 + (qq >> 1) * 8) * 2;
                uint32_t sw = off ^ ((off >> 3) & 0x70);
                LDSM4T(vh, st + FVH + sw);
                LDSM4T(vl, st + FVL + sw);
                MMA16816(O[nd * 2],     aPh[kc], vh[0], vh[1]);
                MMA16816(O[nd * 2],     aPh[kc], vl[0], vl[1]);
                MMA16816(O[nd * 2 + 1], aPh[kc], vh[2], vh[3]);
                MMA16816(O[nd * 2 + 1], aPh[kc], vl[2], vl[3]);
            }
        }
    }

    const float il0 = 1.0f / l0r, il1 = 1.0f / l1r;
    const int r0 = q0 + w * 16 + g;
    const int r1 = r0 + 8;
#pragma unroll
    for (int nt = 0; nt < 8; nt++) {
        const int col = h * 64 + nt * 8 + tg * 2;
        float2 w0 = make_float2(O[nt][0] * il0, O[nt][1] * il0);
        float2 w1 = make_float2(O[nt][2] * il1, O[nt][3] * il1);
        *(float2*)(out + ((size_t)b * 1024 + r0) * 1024 + col) = w0;
        *(float2*)(out + ((size_t)b * 1024 + r1) * 1024 + col) = w1;
    }
}

// ================= kernel_launch =================
extern "C" void kernel_launch(void* const* d_in, const int* in_sizes, int n_in,
                              void* d_out, int out_size)
{
    const float* q    = (const float*)d_in[0];
    const float* k    = (const float*)d_in[1];
    const float* v    = (const float*)d_in[2];
    const float* beta = (const float*)d_in[3];
    const unsigned char* srcm = (const unsigned char*)d_in[4];
    const unsigned char* tgtm = (const unsigned char*)d_in[5];
    const float* Wq = (const float*)d_in[6];
    const float* bq = (const float*)d_in[7];
    const float* Wk = (const float*)d_in[8];
    const float* bk = (const float*)d_in[9];
    const float* Wv = (const float*)d_in[10];
    const float* bv = (const float*)d_in[11];
    float* out = (float*)d_out;

    void *ah, *al;
    cudaGetSymbolAddress(&ah, g_ah);
    cudaGetSymbolAddress(&al, g_al);
    __nv_bfloat16* AH = (__nv_bfloat16*)ah;
    __nv_bfloat16* AL = (__nv_bfloat16*)al;

    cudaFuncSetAttribute(gemm_mma<0>, cudaFuncAttributeMaxDynamicSharedMemorySize, GSMEM_TOTAL);
    cudaFuncSetAttribute(gemm_mma<1>, cudaFuncAttributeMaxDynamicSharedMemorySize, GSMEM_TOTAL);
    cudaFuncSetAttribute(flash_tc, cudaFuncAttributeMaxDynamicSharedMemorySize, FSMEM);

    mask_convert<<<1, 1024>>>(srcm, Bb * TK, 0);
    mask_convert<<<1, 1024>>>(tgtm, Bb * TQ, 1);

    // fused conversion of all activations + weights
    conv_all<<<27648, 256>>>((const float4*)q, (const float4*)k, (const float4*)v,
                             (const float4*)Wq, (const float4*)Wk, (const float4*)Wv);

    // fused QKV projection
    gemm_mma<0><<<dim3(24, 64), 256, GSMEM_TOTAL>>>(bq, bk, bv, nullptr);

    // tensor-core flash attention (writes out)
    flash_tc<<<dim3(TQ / 128, NH, Bb), 256, FSMEM>>>(out);

    // beta @ V accumulated into out
    const int n4_beta = (NH * TQ * TK) / 4;
    conv_split<<<(n4_beta + 255) / 256, 256>>>((const float4*)beta, AH, AL, n4_beta);
    gemm_mma<1><<<dim3(4, 8, 16), 256, GSMEM_TOTAL>>>(nullptr, nullptr, nullptr, out);
}

// round 8
// speedup vs baseline: 5.3825x; 1.3852x over previous
#include <cuda_runtime.h>
#include <cuda_bf16.h>
#include <math.h>
#include <stdint.h>

// Problem constants
#define Bb    8
#define TQ    1024
#define TK    1024
#define DIMX  1024
#define NH    16
#define HD    64
#define SCALE 0.03125f
#define NEGV  -1.0e9f
#define MROWS (Bb * TQ)
#define SC2L  (0.03125f * 1.44269504088896f)

// ================= PTX helpers =================
__device__ __forceinline__ uint32_t smem_u32(const void* p) {
    uint32_t a;
    asm("{ .reg .u64 t; cvta.to.shared.u64 t, %1; cvt.u32.u64 %0, t; }"
        : "=r"(a) : "l"(p));
    return a;
}
#define CP_ASYNC16(dst_u32, src_ptr) \
    asm volatile("cp.async.cg.shared.global [%0], [%1], 16;" \
        :: "r"(dst_u32), "l"(src_ptr))
#define CP_COMMIT() asm volatile("cp.async.commit_group;" ::: "memory")
#define CP_WAIT(n)  asm volatile("cp.async.wait_group %0;" :: "n"(n) : "memory")

#define LDSM4(r, addr) \
    asm volatile("ldmatrix.sync.aligned.m8n8.x4.shared.b16 {%0,%1,%2,%3}, [%4];" \
        : "=r"((r)[0]), "=r"((r)[1]), "=r"((r)[2]), "=r"((r)[3]) : "r"(addr))
#define LDSM4T(r, addr) \
    asm volatile("ldmatrix.sync.aligned.m8n8.x4.trans.shared.b16 {%0,%1,%2,%3}, [%4];" \
        : "=r"((r)[0]), "=r"((r)[1]), "=r"((r)[2]), "=r"((r)[3]) : "r"(addr))

#define MMA16816(c, a, b0, b1) \
    asm volatile("mma.sync.aligned.m16n8k16.row.col.f32.bf16.bf16.f32 " \
        "{%0,%1,%2,%3}, {%4,%5,%6,%7}, {%8,%9}, {%0,%1,%2,%3};" \
        : "+f"((c)[0]), "+f"((c)[1]), "+f"((c)[2]), "+f"((c)[3]) \
        : "r"((a)[0]), "r"((a)[1]), "r"((a)[2]), "r"((a)[3]), "r"(b0), "r"(b1))

__device__ __forceinline__ uint32_t pbf2(float lo, float hi) {
    uint32_t d;
    asm("cvt.rn.bf16x2.f32 %0, %1, %2;" : "=r"(d) : "f"(hi), "f"(lo));
    return d;
}
__device__ __forceinline__ float ex2f(float x) {
    float y;
    asm("ex2.approx.ftz.f32 %0, %1;" : "=f"(y) : "f"(x));
    return y;
}

// ================= scratch =================
__device__ __align__(16) __nv_bfloat16 g_qph[(size_t)MROWS * DIMX];
__device__ __align__(16) __nv_bfloat16 g_kph[(size_t)MROWS * DIMX];
__device__ __align__(16) __nv_bfloat16 g_vph[(size_t)MROWS * DIMX];
__device__ __align__(16) __nv_bfloat16 g_vpl[(size_t)MROWS * DIMX];
__device__ __align__(16) __nv_bfloat16 g_ah[(size_t)24 * 1024 * 1024];  // acts q|k|v, or beta
__device__ __align__(16) __nv_bfloat16 g_al[(size_t)24 * 1024 * 1024];
__device__ __align__(16) __nv_bfloat16 g_bh[(size_t)3 * 1024 * 1024];
__device__ __align__(16) __nv_bfloat16 g_bl[(size_t)3 * 1024 * 1024];
__device__ unsigned char g_src8[Bb * TK];
__device__ unsigned char g_tgt8[Bb * TQ];

// ================= mask canonicalization =================
__global__ void mask_convert(const unsigned char* __restrict__ raw, int n, int which)
{
    __shared__ int has3F, oddNZ;
    if (threadIdx.x == 0) { has3F = 0; oddNZ = 0; }
    __syncthreads();
    int lf = 0, lo = 0;
    for (int i = threadIdx.x; i < n; i += blockDim.x) {
        unsigned char c = raw[i];
        if (c == 0x3F) lf = 1;
        if ((i & 3) && c) lo = 1;
    }
    if (lf) atomicOr(&has3F, 1);
    if (lo) atomicOr(&oddNZ, 1);
    __syncthreads();
    unsigned char* out = which ? g_tgt8 : g_src8;
    int mode = has3F ? 2 : (oddNZ ? 0 : 1);
    for (int i = threadIdx.x; i < n; i += blockDim.x) {
        unsigned char v;
        if (mode == 2)      v = (((const float*)raw)[i] != 0.0f) ? 1 : 0;
        else if (mode == 1) v = (((const int*)raw)[i]   != 0)    ? 1 : 0;
        else                v = (raw[i] != 0) ? 1 : 0;
        out[i] = v;
    }
}

// ================= fp32 -> bf16 conversions =================
__device__ __forceinline__ void split_store(const float4* __restrict__ x,
                                            __nv_bfloat16* __restrict__ hi,
                                            __nv_bfloat16* __restrict__ lo, size_t i)
{
    float4 f = x[i];
    __nv_bfloat16 h0 = __float2bfloat16_rn(f.x);
    __nv_bfloat16 h1 = __float2bfloat16_rn(f.y);
    __nv_bfloat16 h2 = __float2bfloat16_rn(f.z);
    __nv_bfloat16 h3 = __float2bfloat16_rn(f.w);
    __nv_bfloat16 l0 = __float2bfloat16_rn(f.x - __bfloat162float(h0));
    __nv_bfloat16 l1 = __float2bfloat16_rn(f.y - __bfloat162float(h1));
    __nv_bfloat16 l2 = __float2bfloat16_rn(f.z - __bfloat162float(h2));
    __nv_bfloat16 l3 = __float2bfloat16_rn(f.w - __bfloat162float(h3));
    __nv_bfloat162* Hp = (__nv_bfloat162*)(hi + 4 * i);
    __nv_bfloat162* Lp = (__nv_bfloat162*)(lo + 4 * i);
    Hp[0] = __halves2bfloat162(h0, h1);
    Hp[1] = __halves2bfloat162(h2, h3);
    Lp[0] = __halves2bfloat162(l0, l1);
    Lp[1] = __halves2bfloat162(l2, l3);
}
__device__ __forceinline__ void hi_store(const float4* __restrict__ x,
                                         __nv_bfloat16* __restrict__ hi, size_t i)
{
    float4 f = x[i];
    __nv_bfloat162* Hp = (__nv_bfloat162*)(hi + 4 * i);
    Hp[0] = __halves2bfloat162(__float2bfloat16_rn(f.x), __float2bfloat16_rn(f.y));
    Hp[1] = __halves2bfloat162(__float2bfloat16_rn(f.z), __float2bfloat16_rn(f.w));
}

__global__ __launch_bounds__(256)
void conv_split(const float4* __restrict__ x, __nv_bfloat16* __restrict__ hi,
                __nv_bfloat16* __restrict__ lo, int n4)
{
    int i = blockIdx.x * 256 + threadIdx.x;
    if (i >= n4) return;
    split_store(x, hi, lo, i);
}

// q,k hi-only; v hi+lo; Wq,Wk hi-only; Wv hi+lo
__global__ __launch_bounds__(256)
void conv_all(const float4* __restrict__ q, const float4* __restrict__ k,
              const float4* __restrict__ v, const float4* __restrict__ wq,
              const float4* __restrict__ wk, const float4* __restrict__ wv)
{
    const size_t ACT = (size_t)8 * 1024 * 1024;
    const size_t WSEG = (size_t)1024 * 1024;
    int bid = blockIdx.x;
    if (bid < 24576) {
        int seg = bid >> 13;
        size_t i = ((size_t)(bid & 8191)) * 256 + threadIdx.x;
        if (seg == 2) split_store(v, g_ah + 2 * ACT, g_al + 2 * ACT, i);
        else          hi_store(seg ? k : q, g_ah + seg * ACT, i);
    } else {
        bid -= 24576;
        int seg = bid >> 10;
        size_t i = ((size_t)(bid & 1023)) * 256 + threadIdx.x;
        if (seg == 2) split_store(wv, g_bh + 2 * WSEG, g_bl + 2 * WSEG, i);
        else          hi_store(seg ? wk : wq, g_bh + seg * WSEG, i);
    }
}

extern __shared__ char smem_raw[];

// ================= gemm_qk: 1-pass bf16, 2 CTAs/SM =================
// Y[bm+128, bn+128] = bf16(A @ W^T + bias), segs 0(Q)/1(K)
#define QK_STG 32768
#define QK_SMEM (3 * QK_STG)

__global__ __launch_bounds__(256, 2)
void gemm_qk(const float* __restrict__ bias0, const float* __restrict__ bias1)
{
    const uint32_t sb = smem_u32(smem_raw);
    const int tid  = threadIdx.x;
    const int lane = tid & 31;
    const int wid  = tid >> 5;
    const int wm = (wid >> 2) * 64;
    const int wn = (wid & 3) * 32;

    const int seg = blockIdx.x >> 3;
    const int bn  = (blockIdx.x & 7) * 128;
    const int bm  = blockIdx.y * 128;
    const __nv_bfloat16* Ahg = g_ah + (size_t)seg * 8 * 1024 * 1024;
    const __nv_bfloat16* Bhg = g_bh + (size_t)seg * 1024 * 1024;
    const float* bias = seg ? bias1 : bias0;
    __nv_bfloat16* Yh = seg ? g_kph : g_qph;

    float C[4][4][4];
#pragma unroll
    for (int i = 0; i < 4; i++)
#pragma unroll
        for (int j = 0; j < 4; j++)
#pragma unroll
            for (int r = 0; r < 4; r++) C[i][j][r] = 0.0f;

    auto load_stage = [&](int s, int kc) {
        const uint32_t st = sb + s * QK_STG;
        const int koff = kc * 64;
#pragma unroll
        for (int i = 0; i < 4; i++) {
            int idx = tid + i * 256;
            int row = idx >> 3, c = idx & 7;
            uint32_t off = row * 128 + c * 16;
            uint32_t sw = off ^ ((off >> 3) & 0x70);
            CP_ASYNC16(st + sw,         Ahg + (size_t)(bm + row) * 1024 + koff + c * 8);
            CP_ASYNC16(st + 16384 + sw, Bhg + (size_t)(bn + row) * 1024 + koff + c * 8);
        }
        CP_COMMIT();
    };

    const int q  = lane >> 3;
    const int lr = lane & 7;
    const int am_row = wm + (q & 1) * 8 + lr;
    const int a_kq   = (q >> 1) * 16;
    const int bn_row = wn + (q >> 1) * 8 + lr;
    const int b_kq   = (q & 1) * 16;

    load_stage(0, 0);
    load_stage(1, 1);

    for (int kc = 0; kc < 16; kc++) {
        if (kc < 15) CP_WAIT(1); else CP_WAIT(0);
        __syncthreads();
        if (kc + 2 < 16) load_stage((kc + 2) % 3, kc + 2);

        const uint32_t st = sb + (kc % 3) * QK_STG;
#pragma unroll
        for (int ks = 0; ks < 4; ks++) {
            uint32_t aH[4][4], bH[2][4];
#pragma unroll
            for (int i = 0; i < 4; i++) {
                uint32_t off = (uint32_t)(am_row + i * 16) * 128 + a_kq + ks * 32;
                uint32_t sw = off ^ ((off >> 3) & 0x70);
                LDSM4(aH[i], st + sw);
            }
#pragma unroll
            for (int j2 = 0; j2 < 2; j2++) {
                uint32_t off = (uint32_t)(bn_row + j2 * 16) * 128 + b_kq + ks * 32;
                uint32_t sw = off ^ ((off >> 3) & 0x70);
                LDSM4(bH[j2], st + 16384 + sw);
            }
#pragma unroll
            for (int i = 0; i < 4; i++)
#pragma unroll
                for (int j = 0; j < 4; j++) {
                    const int jj = j >> 1, jo = (j & 1) * 2;
                    MMA16816(C[i][j], aH[i], bH[jj][jo], bH[jj][jo + 1]);
                }
        }
    }

    const int g  = lane >> 2;
    const int tg = lane & 3;
#pragma unroll
    for (int i = 0; i < 4; i++)
#pragma unroll
        for (int j = 0; j < 4; j++) {
            const int col = bn + wn + j * 8 + tg * 2;
            const int r0 = bm + wm + i * 16 + g;
            float b0v = bias[col], b1v = bias[col + 1];
            *(uint32_t*)(Yh + (size_t)r0 * 1024 + col) = pbf2(C[i][j][0] + b0v, C[i][j][1] + b1v);
            *(uint32_t*)(Yh + (size_t)(r0 + 8) * 1024 + col) = pbf2(C[i][j][2] + b0v, C[i][j][3] + b1v);
        }
}

// ================= gemm_v / gemm_beta (3-pass) =================
#define STG_B 65536
#define GSMEM_TOTAL (3 * STG_B)

// MODE 0: V projection (hi/lo out). MODE 1: beta@V accumulate into out.
template <int MODE>
__global__ __launch_bounds__(256)
void gemm_mma(const float* __restrict__ bias2, float* __restrict__ Yf)
{
    const uint32_t sb = smem_u32(smem_raw);
    const int tid  = threadIdx.x;
    const int lane = tid & 31;
    const int wid  = tid >> 5;
    const int wm = (wid >> 2) * 64;
    const int wn = (wid & 3) * 32;

    int bm, bn = 0, h = 0, b0 = 0;
    size_t arow0;
    const __nv_bfloat16 *Ahg, *Alg, *Bhg = nullptr, *Blg = nullptr;
    if (MODE == 0) {
        bn = blockIdx.x * 128; bm = blockIdx.y * 128;
        arow0 = (size_t)bm;
        Ahg = g_ah + (size_t)2 * 8 * 1024 * 1024;
        Alg = g_al + (size_t)2 * 8 * 1024 * 1024;
        Bhg = g_bh + (size_t)2 * 1024 * 1024;
        Blg = g_bl + (size_t)2 * 1024 * 1024;
    } else {
        b0 = blockIdx.x * 2; bm = blockIdx.y * 128; h = blockIdx.z;
        arow0 = (size_t)h * 1024 + bm;
        Ahg = g_ah; Alg = g_al;
    }

    float C[4][4][4];
#pragma unroll
    for (int i = 0; i < 4; i++)
#pragma unroll
        for (int j = 0; j < 4; j++)
#pragma unroll
            for (int r = 0; r < 4; r++) C[i][j][r] = 0.0f;

    auto load_stage = [&](int s, int kc) {
        const uint32_t st = sb + s * STG_B;
        const int koff = kc * 64;
#pragma unroll
        for (int i = 0; i < 4; i++) {
            int idx = tid + i * 256;
            int row = idx >> 3, c = idx & 7;
            uint32_t off = row * 128 + c * 16;
            uint32_t sw = off ^ ((off >> 3) & 0x70);
            size_t gA = (arow0 + row) * 1024 + koff + c * 8;
            CP_ASYNC16(st + sw,         Ahg + gA);
            CP_ASYNC16(st + 16384 + sw, Alg + gA);
        }
        if (MODE == 0) {
#pragma unroll
            for (int i = 0; i < 4; i++) {
                int idx = tid + i * 256;
                int row = idx >> 3, c = idx & 7;
                uint32_t off = row * 128 + c * 16;
                uint32_t sw = off ^ ((off >> 3) & 0x70);
                size_t gB = (size_t)(bn + row) * 1024 + koff + c * 8;
                CP_ASYNC16(st + 32768 + sw, Bhg + gB);
                CP_ASYNC16(st + 49152 + sw, Blg + gB);
            }
        } else {
#pragma unroll
            for (int i = 0; i < 4; i++) {
                int idx = tid + i * 256;
                int half = idx >> 9, row = (idx >> 3) & 63, c = idx & 7;
                uint32_t off = row * 128 + c * 16;
                uint32_t sw = off ^ ((off >> 3) & 0x70);
                size_t gV = ((size_t)(b0 + half) * 1024 + koff + row) * 1024 + h * 64 + c * 8;
                CP_ASYNC16(st + 32768 + half * 8192 + sw, g_vph + gV);
                CP_ASYNC16(st + 49152 + half * 8192 + sw, g_vpl + gV);
            }
        }
        CP_COMMIT();
    };

    const int q  = lane >> 3;
    const int lr = lane & 7;
    const int am_row = wm + (q & 1) * 8 + lr;
    const int a_kq   = (q >> 1) * 16;
    const int bn_row = wn + (q >> 1) * 8 + lr;
    const int b_kq   = (q & 1) * 16;

    load_stage(0, 0);
    load_stage(1, 1);

    for (int kc = 0; kc < 16; kc++) {
        if (kc < 15) CP_WAIT(1); else CP_WAIT(0);
        __syncthreads();
        if (kc + 2 < 16) load_stage((kc + 2) % 3, kc + 2);

        const uint32_t st = sb + (kc % 3) * STG_B;
#pragma unroll
        for (int ks = 0; ks < 4; ks++) {
            uint32_t aH[4][4], aL[4][4], bH[2][4], bL[2][4];
#pragma unroll
            for (int i = 0; i < 4; i++) {
                uint32_t off = (uint32_t)(am_row + i * 16) * 128 + a_kq + ks * 32;
                uint32_t sw = off ^ ((off >> 3) & 0x70);
                LDSM4(aH[i], st + sw);
                LDSM4(aL[i], st + 16384 + sw);
            }
#pragma unroll
            for (int j2 = 0; j2 < 2; j2++) {
                if (MODE == 0) {
                    uint32_t off = (uint32_t)(bn_row + j2 * 16) * 128 + b_kq + ks * 32;
                    uint32_t sw = off ^ ((off >> 3) & 0x70);
                    LDSM4(bH[j2], st + 32768 + sw);
                    LDSM4(bL[j2], st + 49152 + sw);
                } else {
                    const int n16 = wn + j2 * 16;
                    const int half = n16 >> 6, d0 = n16 & 63;
                    uint32_t off = (uint32_t)(ks * 16 + (q & 1) * 8 + lr) * 128 +
                                   (d0 + (q >> 1) * 8) * 2;
                    uint32_t sw = off ^ ((off >> 3) & 0x70);
                    LDSM4T(bH[j2], st + 32768 + half * 8192 + sw);
                    LDSM4T(bL[j2], st + 49152 + half * 8192 + sw);
                }
            }
#pragma unroll
            for (int i = 0; i < 4; i++)
#pragma unroll
                for (int j = 0; j < 4; j++) {
                    const int jj = j >> 1, jo = (j & 1) * 2;
                    MMA16816(C[i][j], aH[i], bH[jj][jo], bH[jj][jo + 1]);
                    MMA16816(C[i][j], aH[i], bL[jj][jo], bL[jj][jo + 1]);
                    MMA16816(C[i][j], aL[i], bH[jj][jo], bH[jj][jo + 1]);
                }
        }
    }

    const int g  = lane >> 2;
    const int tg = lane & 3;
#pragma unroll
    for (int i = 0; i < 4; i++) {
#pragma unroll
        for (int j = 0; j < 4; j++) {
            const int ncol = wn + j * 8 + tg * 2;
            const int r0 = bm + wm + i * 16 + g;
            const int r1 = r0 + 8;
            if (MODE == 0) {
                const int col = bn + ncol;
                float b0v = bias2[col], b1v = bias2[col + 1];
                float y00 = C[i][j][0] + b0v, y01 = C[i][j][1] + b1v;
                float y10 = C[i][j][2] + b0v, y11 = C[i][j][3] + b1v;
                float l00 = y00 - __bfloat162float(__float2bfloat16_rn(y00));
                float l01 = y01 - __bfloat162float(__float2bfloat16_rn(y01));
                float l10 = y10 - __bfloat162float(__float2bfloat16_rn(y10));
                float l11 = y11 - __bfloat162float(__float2bfloat16_rn(y11));
                *(uint32_t*)(g_vph + (size_t)r0 * 1024 + col) = pbf2(y00, y01);
                *(uint32_t*)(g_vph + (size_t)r1 * 1024 + col) = pbf2(y10, y11);
                *(uint32_t*)(g_vpl + (size_t)r0 * 1024 + col) = pbf2(l00, l01);
                *(uint32_t*)(g_vpl + (size_t)r1 * 1024 + col) = pbf2(l10, l11);
            } else {
                const int n = blockIdx.x * 128 + ncol;
                const int bb = n >> 6, dd = n & 63;
                float* p0 = Yf + ((size_t)bb * 1024 + r0) * 1024 + h * 64 + dd;
                float* p1 = Yf + ((size_t)bb * 1024 + r1) * 1024 + h * 64 + dd;
                float2 o0 = *(float2*)p0, o1 = *(float2*)p1;
                o0.x += C[i][j][0]; o0.y += C[i][j][1];
                o1.x += C[i][j][2]; o1.y += C[i][j][3];
                *(float2*)p0 = o0;
                *(float2*)p1 = o1;
            }
        }
    }
}

// ================= flash attention (S 1-pass, PV hi-only) =================
#define FQH 0
#define FST0 16384
#define FKH 0
#define FVH 8192
#define FSRC 16384
#define FSTG 16512
#define FSMEM (16384 + 3 * FSTG)

__global__ __launch_bounds__(256, 2)
void flash_tc(float* __restrict__ out)
{
    char* sm = smem_raw;
    const uint32_t sb = smem_u32(sm);
    const int tid  = threadIdx.x;
    const int lane = tid & 31;
    const int w    = tid >> 5;
    const int q0 = blockIdx.x * 128;
    const int h  = blockIdx.y;
    const int b  = blockIdx.z;
    const int g  = lane >> 2;
    const int tg = lane & 3;
    const int qq = lane >> 3;
    const int lr = lane & 7;

    {
#pragma unroll
        for (int i = 0; i < 4; i++) {
            int idx = tid + i * 256;
            int row = idx >> 3, c = idx & 7;
            uint32_t off = row * 128 + c * 16;
            uint32_t sw = off ^ ((off >> 3) & 0x70);
            size_t gq = ((size_t)b * 1024 + q0 + row) * 1024 + h * 64 + c * 8;
            CP_ASYNC16(sb + FQH + sw, g_qph + gq);
        }
        CP_COMMIT();
    }

    auto load_stage = [&](int s, int kt) {
        const uint32_t st = sb + FST0 + s * FSTG;
        const int k0 = kt * 64;
#pragma unroll
        for (int i = 0; i < 2; i++) {
            int idx = tid + i * 256;
            int row = idx >> 3, c = idx & 7;
            uint32_t off = row * 128 + c * 16;
            uint32_t sw = off ^ ((off >> 3) & 0x70);
            size_t gk = ((size_t)b * 1024 + k0 + row) * 1024 + h * 64 + c * 8;
            CP_ASYNC16(st + FKH + sw, g_kph + gk);
            CP_ASYNC16(st + FVH + sw, g_vph + gk);
        }
        if (tid < 4)
            CP_ASYNC16(st + FSRC + tid * 16, g_src8 + b * 1024 + k0 + tid * 16);
        CP_COMMIT();
    };

    load_stage(0, 0);
    load_stage(1, 1);

    const unsigned char t0m = g_tgt8[b * 1024 + q0 + w * 16 + g];
    const unsigned char t1m = g_tgt8[b * 1024 + q0 + w * 16 + 8 + g];

    float m0r = -3.0e38f, m1r = -3.0e38f, l0r = 0.0f, l1r = 0.0f;
    float O[8][4];
#pragma unroll
    for (int i = 0; i < 8; i++)
#pragma unroll
        for (int r = 0; r < 4; r++) O[i][r] = 0.0f;

    uint32_t aQh[4][4];

    for (int kt = 0; kt < 16; kt++) {
        if (kt < 15) CP_WAIT(1); else CP_WAIT(0);
        __syncthreads();
        if (kt + 2 < 16) load_stage((kt + 2) % 3, kt + 2);

        if (kt == 0) {
#pragma unroll
            for (int kc = 0; kc < 4; kc++) {
                uint32_t off = (uint32_t)(w * 16 + (qq & 1) * 8 + lr) * 128 + (qq >> 1) * 16 + kc * 32;
                uint32_t sw = off ^ ((off >> 3) & 0x70);
                LDSM4(aQh[kc], sb + FQH + sw);
            }
        }

        const uint32_t st = sb + FST0 + (kt % 3) * FSTG;
        char* stp = sm + FST0 + (kt % 3) * FSTG;

        // ---- S = Qh @ Kh^T ----
        float C[8][4];
#pragma unroll
        for (int i = 0; i < 8; i++)
#pragma unroll
            for (int r = 0; r < 4; r++) C[i][r] = 0.0f;
#pragma unroll
        for (int ks = 0; ks < 4; ks++) {
#pragma unroll
            for (int j2 = 0; j2 < 4; j2++) {
                uint32_t bh[4];
                uint32_t off = (uint32_t)(j2 * 16 + (qq >> 1) * 8 + lr) * 128 + (qq & 1) * 16 + ks * 32;
                uint32_t sw = off ^ ((off >> 3) & 0x70);
                LDSM4(bh, st + FKH + sw);
                MMA16816(C[j2 * 2],     aQh[ks], bh[0], bh[1]);
                MMA16816(C[j2 * 2 + 1], aQh[ks], bh[2], bh[3]);
            }
        }

        // ---- mask + online softmax (log2 domain) ----
        float mx0 = -3.0e38f, mx1 = -3.0e38f;
#pragma unroll
        for (int nt = 0; nt < 8; nt++) {
            unsigned char s0 = *(unsigned char*)(stp + FSRC + nt * 8 + tg * 2);
            unsigned char s1 = *(unsigned char*)(stp + FSRC + nt * 8 + tg * 2 + 1);
            C[nt][0] = (t0m && s0) ? C[nt][0] * SC2L : NEGV;
            C[nt][1] = (t0m && s1) ? C[nt][1] * SC2L : NEGV;
            C[nt][2] = (t1m && s0) ? C[nt][2] * SC2L : NEGV;
            C[nt][3] = (t1m && s1) ? C[nt][3] * SC2L : NEGV;
            mx0 = fmaxf(mx0, fmaxf(C[nt][0], C[nt][1]));
            mx1 = fmaxf(mx1, fmaxf(C[nt][2], C[nt][3]));
        }
        mx0 = fmaxf(mx0, __shfl_xor_sync(0xFFFFFFFF, mx0, 1));
        mx0 = fmaxf(mx0, __shfl_xor_sync(0xFFFFFFFF, mx0, 2));
        mx1 = fmaxf(mx1, __shfl_xor_sync(0xFFFFFFFF, mx1, 1));
        mx1 = fmaxf(mx1, __shfl_xor_sync(0xFFFFFFFF, mx1, 2));

        float mn0 = fmaxf(m0r, mx0), mn1 = fmaxf(m1r, mx1);
        float f0 = ex2f(m0r - mn0), f1 = ex2f(m1r - mn1);
        m0r = mn0; m1r = mn1;

        float s0 = 0.0f, s1 = 0.0f;
#pragma unroll
        for (int nt = 0; nt < 8; nt++) {
            C[nt][0] = ex2f(C[nt][0] - mn0);
            C[nt][1] = ex2f(C[nt][1] - mn0);
            C[nt][2] = ex2f(C[nt][2] - mn1);
            C[nt][3] = ex2f(C[nt][3] - mn1);
            s0 += C[nt][0] + C[nt][1];
            s1 += C[nt][2] + C[nt][3];
        }
        s0 += __shfl_xor_sync(0xFFFFFFFF, s0, 1);
        s0 += __shfl_xor_sync(0xFFFFFFFF, s0, 2);
        s1 += __shfl_xor_sync(0xFFFFFFFF, s1, 1);
        s1 += __shfl_xor_sync(0xFFFFFFFF, s1, 2);
        l0r = l0r * f0 + s0;
        l1r = l1r * f1 + s1;

#pragma unroll
        for (int nt = 0; nt < 8; nt++) {
            O[nt][0] *= f0; O[nt][1] *= f0;
            O[nt][2] *= f1; O[nt][3] *= f1;
        }

        // ---- pack P (hi only) ----
        uint32_t aPh[4][4];
#pragma unroll
        for (int kc = 0; kc < 4; kc++) {
            const int n0 = kc * 2, n1 = kc * 2 + 1;
            aPh[kc][0] = pbf2(C[n0][0], C[n0][1]);
            aPh[kc][1] = pbf2(C[n0][2], C[n0][3]);
            aPh[kc][2] = pbf2(C[n1][0], C[n1][1]);
            aPh[kc][3] = pbf2(C[n1][2], C[n1][3]);
        }

        // ---- O += Ph @ Vh ----
#pragma unroll
        for (int kc = 0; kc < 4; kc++) {
#pragma unroll
            for (int nd = 0; nd < 4; nd++) {
                uint32_t vh[4];
                uint32_t off = (uint32_t)(kc * 16 + (qq & 1) * 8 + lr) * 128 +
                               (nd * 16 + (qq >> 1) * 8) * 2;
                uint32_t sw = off ^ ((off >> 3) & 0x70);
                LDSM4T(vh, st + FVH + sw);
                MMA16816(O[nd * 2],     aPh[kc], vh[0], vh[1]);
                MMA16816(O[nd * 2 + 1], aPh[kc], vh[2], vh[3]);
            }
        }
    }

    const float il0 = 1.0f / l0r, il1 = 1.0f / l1r;
    const int r0 = q0 + w * 16 + g;
    const int r1 = r0 + 8;
#pragma unroll
    for (int nt = 0; nt < 8; nt++) {
        const int col = h * 64 + nt * 8 + tg * 2;
        float2 w0 = make_float2(O[nt][0] * il0, O[nt][1] * il0);
        float2 w1 = make_float2(O[nt][2] * il1, O[nt][3] * il1);
        *(float2*)(out + ((size_t)b * 1024 + r0) * 1024 + col) = w0;
        *(float2*)(out + ((size_t)b * 1024 + r1) * 1024 + col) = w1;
    }
}

// ================= kernel_launch =================
extern "C" void kernel_launch(void* const* d_in, const int* in_sizes, int n_in,
                              void* d_out, int out_size)
{
    const float* q    = (const float*)d_in[0];
    const float* k    = (const float*)d_in[1];
    const float* v    = (const float*)d_in[2];
    const float* beta = (const float*)d_in[3];
    const unsigned char* srcm = (const unsigned char*)d_in[4];
    const unsigned char* tgtm = (const unsigned char*)d_in[5];
    const float* Wq = (const float*)d_in[6];
    const float* bq = (const float*)d_in[7];
    const float* Wk = (const float*)d_in[8];
    const float* bk = (const float*)d_in[9];
    const float* Wv = (const float*)d_in[10];
    const float* bv = (const float*)d_in[11];
    float* out = (float*)d_out;

    void *ah, *al;
    cudaGetSymbolAddress(&ah, g_ah);
    cudaGetSymbolAddress(&al, g_al);
    __nv_bfloat16* AH = (__nv_bfloat16*)ah;
    __nv_bfloat16* AL = (__nv_bfloat16*)al;

    cudaFuncSetAttribute(gemm_qk,     cudaFuncAttributeMaxDynamicSharedMemorySize, QK_SMEM);
    cudaFuncSetAttribute(gemm_mma<0>, cudaFuncAttributeMaxDynamicSharedMemorySize, GSMEM_TOTAL);
    cudaFuncSetAttribute(gemm_mma<1>, cudaFuncAttributeMaxDynamicSharedMemorySize, GSMEM_TOTAL);
    cudaFuncSetAttribute(flash_tc,    cudaFuncAttributeMaxDynamicSharedMemorySize, FSMEM);

    mask_convert<<<1, 1024>>>(srcm, Bb * TK, 0);
    mask_convert<<<1, 1024>>>(tgtm, Bb * TQ, 1);

    conv_all<<<27648, 256>>>((const float4*)q, (const float4*)k, (const float4*)v,
                             (const float4*)Wq, (const float4*)Wk, (const float4*)Wv);

    // Q,K projections (1-pass bf16, 2 CTAs/SM)
    gemm_qk<<<dim3(16, 64), 256, QK_SMEM>>>(bq, bk);
    // V projection (3-pass split)
    gemm_mma<0><<<dim3(8, 64), 256, GSMEM_TOTAL>>>(bv, nullptr);

    // flash attention (writes out)
    flash_tc<<<dim3(TQ / 128, NH, Bb), 256, FSMEM>>>(out);

    // beta @ V accumulated into out
    const int n4_beta = (NH * TQ * TK) / 4;
    conv_split<<<(n4_beta + 255) / 256, 256>>>((const float4*)beta, AH, AL, n4_beta);
    gemm_mma<1><<<dim3(4, 8, 16), 256, GSMEM_TOTAL>>>(nullptr, out);
}